// round 1
// baseline (speedup 1.0000x reference)
#include <cuda_runtime.h>
#include <stdint.h>
#include <math.h>

#define NN 50000
#define NE 800000
#define NF 512
#define NH 128
#define NL 16

typedef unsigned long long ull;

// ---------------- scratch (device globals: allocation-free) ----------------
__device__ int   g_deg[NN];
__device__ int   g_rowptr[NN + 1];
__device__ int   g_colidx[NE];
__device__ float g_wval[NE];
__device__ float g_dinv[NN];
__device__ __align__(16) float g_h0[(size_t)NN * NH];
__device__ __align__(16) float g_hA[(size_t)NN * NH];
__device__ __align__(16) float g_hB[(size_t)NN * NH];
__device__ __align__(16) float g_hi[(size_t)NN * NH];

// ---------------- packed fp32x2 helpers (Blackwell) ----------------
__device__ __forceinline__ ull ffma2(ull a, ull b, ull c) {
    ull d;
    asm("fma.rn.f32x2 %0, %1, %2, %3;" : "=l"(d) : "l"(a), "l"(b), "l"(c));
    return d;
}
__device__ __forceinline__ ull pack2(float s) {
    ull d;
    asm("mov.b64 %0, {%1, %1};" : "=l"(d) : "f"(s));
    return d;
}
union F2U { ull u; float2 f; };

// ---------------- graph preprocessing ----------------
__global__ void k_zero() {
    int i = blockIdx.x * blockDim.x + threadIdx.x;
    if (i < NN) g_deg[i] = 0;
}

__global__ void k_count(const int* __restrict__ row) {
    int e = blockIdx.x * blockDim.x + threadIdx.x;
    if (e < NE) atomicAdd(&g_deg[row[e]], 1);
}

__global__ void k_dinv() {
    int i = blockIdx.x * blockDim.x + threadIdx.x;
    if (i < NN) g_dinv[i] = rsqrtf((float)(g_deg[i] + 1));  // +1 self loop
}

__global__ void k_scan() {
    __shared__ int ss[1024];
    const int C = (NN + 1023) / 1024;  // 49
    int t = threadIdx.x;
    int base = t * C;
    int s = 0;
    for (int i = 0; i < C; i++) {
        int idx = base + i;
        if (idx < NN) s += g_deg[idx];
    }
    ss[t] = s;
    __syncthreads();
    for (int off = 1; off < 1024; off <<= 1) {
        int v = (t >= off) ? ss[t - off] : 0;
        __syncthreads();
        ss[t] += v;
        __syncthreads();
    }
    int run = (t == 0) ? 0 : ss[t - 1];
    for (int i = 0; i < C; i++) {
        int idx = base + i;
        if (idx < NN) {
            int d = g_deg[idx];
            g_rowptr[idx] = run;
            g_deg[idx]    = run;   // becomes fill cursor
            run += d;
        }
    }
    if (t == 1023) g_rowptr[NN] = ss[1023];
}

__global__ void k_scatter(const int* __restrict__ row, const int* __restrict__ col) {
    int e = blockIdx.x * blockDim.x + threadIdx.x;
    if (e < NE) {
        int r = row[e], c = col[e];
        int p = atomicAdd(&g_deg[r], 1);
        g_colidx[p] = c;
        g_wval[p]   = g_dinv[r] * g_dinv[c];
    }
}

// ---------------- GEMM0: h0 = relu(x @ W0 + b0), also copies into hA ----------------
__global__ void __launch_bounds__(256) k_gemm0(const float* __restrict__ x,
                                               const float* __restrict__ w0,
                                               const float* __restrict__ b0) {
    __shared__ __align__(16) float Wsh[64 * 128];
    __shared__ __align__(16) float Xsh[64 * 64];
    int t = threadIdx.x, lane = t & 31, warp = t >> 5;
    int row0 = blockIdx.x * 64;
    ull acc[8][2];
#pragma unroll
    for (int r = 0; r < 8; r++) { acc[r][0] = 0ULL; acc[r][1] = 0ULL; }

    for (int kc = 0; kc < NF; kc += 64) {
        const float4* wsrc = (const float4*)(w0 + (size_t)kc * NH);
        float4* wdst = (float4*)Wsh;
#pragma unroll
        for (int i = 0; i < 8; i++) wdst[t + i * 256] = wsrc[t + i * 256];
#pragma unroll
        for (int i = 0; i < 4; i++) {
            int j = t + i * 256;              // 0..1023
            int rr = j >> 4, cc = j & 15;
            int r = row0 + rr;
            float4 v = make_float4(0.f, 0.f, 0.f, 0.f);
            if (r < NN) v = *(const float4*)(x + (size_t)r * NF + kc + (cc << 2));
            *(float4*)(Xsh + rr * 64 + (cc << 2)) = v;
        }
        __syncthreads();
        const float* sbase = Xsh + warp * 8 * 64;
#pragma unroll 2
        for (int k = 0; k < 64; k++) {
            ulonglong2 wv = *(const ulonglong2*)(Wsh + k * 128 + (lane << 2));
#pragma unroll
            for (int rr = 0; rr < 8; rr++) {
                ull sp = pack2(sbase[rr * 64 + k]);
                acc[rr][0] = ffma2(sp, wv.x, acc[rr][0]);
                acc[rr][1] = ffma2(sp, wv.y, acc[rr][1]);
            }
        }
        __syncthreads();
    }

    float4 bias = *(const float4*)(b0 + (lane << 2));
#pragma unroll
    for (int rr = 0; rr < 8; rr++) {
        int r = row0 + warp * 8 + rr;
        if (r < NN) {
            F2U u0, u1;
            u0.u = acc[rr][0];
            u1.u = acc[rr][1];
            float4 o;
            o.x = fmaxf(u0.f.x + bias.x, 0.f);
            o.y = fmaxf(u0.f.y + bias.y, 0.f);
            o.z = fmaxf(u1.f.x + bias.z, 0.f);
            o.w = fmaxf(u1.f.y + bias.w, 0.f);
            *(float4*)(g_h0 + (size_t)r * NH + (lane << 2)) = o;
            *(float4*)(g_hA + (size_t)r * NH + (lane << 2)) = o;
        }
    }
}

// ---------------- SpMM: hi = (D^-1/2 (A+I) D^-1/2) h ----------------
__global__ void __launch_bounds__(256) k_spmm(int flag) {
    const float* __restrict__ hin = flag ? g_hB : g_hA;
    int wid = (blockIdx.x * 256 + threadIdx.x) >> 5;
    if (wid >= NN) return;
    int lane = threadIdx.x & 31;
    int beg = g_rowptr[wid], end = g_rowptr[wid + 1];
    float di = g_dinv[wid];
    float w2 = di * di;
    float4 hv = *(const float4*)(hin + (size_t)wid * NH + (lane << 2));
    float4 acc = make_float4(w2 * hv.x, w2 * hv.y, w2 * hv.z, w2 * hv.w);
#pragma unroll 2
    for (int e = beg; e < end; e++) {
        int c = g_colidx[e];
        float we = g_wval[e];
        float4 v = *(const float4*)(hin + (size_t)c * NH + (lane << 2));
        acc.x = fmaf(we, v.x, acc.x);
        acc.y = fmaf(we, v.y, acc.y);
        acc.z = fmaf(we, v.z, acc.z);
        acc.w = fmaf(we, v.w, acc.w);
    }
    *(float4*)(g_hi + (size_t)wid * NH + (lane << 2)) = acc;
}

// ---------------- layer: h = relu(theta*(S@W) + (1-theta)*S), S = 0.9*hi + 0.1*h0 ----------------
__global__ void __launch_bounds__(256) k_layer(const float* __restrict__ Wl, float theta, int flag) {
    float* __restrict__ hout = flag ? g_hA : g_hB;
    __shared__ __align__(16) float Wsh[64 * 128];
    __shared__ __align__(16) float Ssh[64 * 64];
    int t = threadIdx.x, lane = t & 31, warp = t >> 5;
    int row0 = blockIdx.x * 64;
    ull acc[8][2];
#pragma unroll
    for (int r = 0; r < 8; r++) { acc[r][0] = 0ULL; acc[r][1] = 0ULL; }

    for (int kc = 0; kc < NH; kc += 64) {
        const float4* wsrc = (const float4*)(Wl + (size_t)kc * NH);
        float4* wdst = (float4*)Wsh;
#pragma unroll
        for (int i = 0; i < 8; i++) wdst[t + i * 256] = wsrc[t + i * 256];
#pragma unroll
        for (int i = 0; i < 4; i++) {
            int j = t + i * 256;
            int rr = j >> 4, cc = j & 15;
            int r = row0 + rr;
            float4 s4 = make_float4(0.f, 0.f, 0.f, 0.f);
            if (r < NN) {
                size_t off = (size_t)r * NH + kc + (cc << 2);
                float4 a = *(const float4*)(g_hi + off);
                float4 b = *(const float4*)(g_h0 + off);
                s4.x = 0.9f * a.x + 0.1f * b.x;
                s4.y = 0.9f * a.y + 0.1f * b.y;
                s4.z = 0.9f * a.z + 0.1f * b.z;
                s4.w = 0.9f * a.w + 0.1f * b.w;
            }
            *(float4*)(Ssh + rr * 64 + (cc << 2)) = s4;
        }
        __syncthreads();
        const float* sbase = Ssh + warp * 8 * 64;
#pragma unroll 2
        for (int k = 0; k < 64; k++) {
            ulonglong2 wv = *(const ulonglong2*)(Wsh + k * 128 + (lane << 2));
#pragma unroll
            for (int rr = 0; rr < 8; rr++) {
                ull sp = pack2(sbase[rr * 64 + k]);
                acc[rr][0] = ffma2(sp, wv.x, acc[rr][0]);
                acc[rr][1] = ffma2(sp, wv.y, acc[rr][1]);
            }
        }
        __syncthreads();
    }

    float omt = 1.0f - theta;
#pragma unroll
    for (int rr = 0; rr < 8; rr++) {
        int r = row0 + warp * 8 + rr;
        if (r < NN) {
            size_t off = (size_t)r * NH + (lane << 2);
            float4 a = *(const float4*)(g_hi + off);
            float4 b = *(const float4*)(g_h0 + off);
            F2U u0, u1;
            u0.u = acc[rr][0];
            u1.u = acc[rr][1];
            float4 o;
            float sx = 0.9f * a.x + 0.1f * b.x;
            float sy = 0.9f * a.y + 0.1f * b.y;
            float sz = 0.9f * a.z + 0.1f * b.z;
            float sw = 0.9f * a.w + 0.1f * b.w;
            o.x = fmaxf(theta * u0.f.x + omt * sx, 0.f);
            o.y = fmaxf(theta * u0.f.y + omt * sy, 0.f);
            o.z = fmaxf(theta * u1.f.x + omt * sz, 0.f);
            o.w = fmaxf(theta * u1.f.y + omt * sw, 0.f);
            *(float4*)(hout + off) = o;
        }
    }
}

// ---------------- final: out = hA @ fc1_w + b1 ----------------
__global__ void __launch_bounds__(256) k_final(const float* __restrict__ w1,
                                               const float* __restrict__ b1,
                                               float* __restrict__ out) {
    __shared__ __align__(16) float Wsh[64 * 128];
    __shared__ __align__(16) float Ssh[64 * 64];
    int t = threadIdx.x, lane = t & 31, warp = t >> 5;
    int row0 = blockIdx.x * 64;
    ull acc[8][2];
#pragma unroll
    for (int r = 0; r < 8; r++) { acc[r][0] = 0ULL; acc[r][1] = 0ULL; }

    for (int kc = 0; kc < NH; kc += 64) {
        const float4* wsrc = (const float4*)(w1 + (size_t)kc * NH);
        float4* wdst = (float4*)Wsh;
#pragma unroll
        for (int i = 0; i < 8; i++) wdst[t + i * 256] = wsrc[t + i * 256];
#pragma unroll
        for (int i = 0; i < 4; i++) {
            int j = t + i * 256;
            int rr = j >> 4, cc = j & 15;
            int r = row0 + rr;
            float4 v = make_float4(0.f, 0.f, 0.f, 0.f);
            if (r < NN) v = *(const float4*)(g_hA + (size_t)r * NH + kc + (cc << 2));
            *(float4*)(Ssh + rr * 64 + (cc << 2)) = v;
        }
        __syncthreads();
        const float* sbase = Ssh + warp * 8 * 64;
#pragma unroll 2
        for (int k = 0; k < 64; k++) {
            ulonglong2 wv = *(const ulonglong2*)(Wsh + k * 128 + (lane << 2));
#pragma unroll
            for (int rr = 0; rr < 8; rr++) {
                ull sp = pack2(sbase[rr * 64 + k]);
                acc[rr][0] = ffma2(sp, wv.x, acc[rr][0]);
                acc[rr][1] = ffma2(sp, wv.y, acc[rr][1]);
            }
        }
        __syncthreads();
    }

    float4 bias = *(const float4*)(b1 + (lane << 2));
#pragma unroll
    for (int rr = 0; rr < 8; rr++) {
        int r = row0 + warp * 8 + rr;
        if (r < NN) {
            F2U u0, u1;
            u0.u = acc[rr][0];
            u1.u = acc[rr][1];
            float4 o;
            o.x = u0.f.x + bias.x;
            o.y = u0.f.y + bias.y;
            o.z = u1.f.x + bias.z;
            o.w = u1.f.y + bias.w;
            *(float4*)(out + (size_t)r * NH + (lane << 2)) = o;
        }
    }
}

// ---------------- launch ----------------
extern "C" void kernel_launch(void* const* d_in, const int* in_sizes, int n_in,
                              void* d_out, int out_size) {
    const float* x    = (const float*)d_in[0];
    const int*   ei   = (const int*)d_in[1];
    const float* cw   = (const float*)d_in[2];
    const float* fc0w = (const float*)d_in[3];
    const float* fc0b = (const float*)d_in[4];
    const float* fc1w = (const float*)d_in[5];
    const float* fc1b = (const float*)d_in[6];
    float* out = (float*)d_out;

    const int* row = ei;
    const int* col = ei + NE;

    k_zero<<<(NN + 255) / 256, 256>>>();
    k_count<<<(NE + 255) / 256, 256>>>(row);
    k_dinv<<<(NN + 255) / 256, 256>>>();
    k_scan<<<1, 1024>>>();
    k_scatter<<<(NE + 255) / 256, 256>>>(row, col);

    int gB = (NN + 63) / 64;
    k_gemm0<<<gB, 256>>>(x, fc0w, fc0b);

    for (int l = 0; l < NL; l++) {
        int flag = l & 1;
        k_spmm<<<(NN * 32 + 255) / 256, 256>>>(flag);
        float theta = logf(0.5f / (float)(l + 1) + 1.0f);
        k_layer<<<gB, 256>>>(cw + (size_t)l * NH * NH, theta, flag);
    }

    k_final<<<gB, 256>>>(fc1w, fc1b, out);
}

// round 4
// speedup vs baseline: 1.1045x; 1.1045x over previous
#include <cuda_runtime.h>
#include <cuda_fp16.h>
#include <stdint.h>
#include <math.h>

#define NN 50000
#define NE 800000
#define NF 512
#define NH 128
#define NL 16

typedef unsigned long long ull;

// ---------------- scratch (device globals: allocation-free) ----------------
__device__ int   g_deg[NN];
__device__ int   g_rowptr[NN + 1];
__device__ int   g_incl[NN];
__device__ int   g_bsum[64];
__device__ ull   g_ecw[NE];            // packed (col, weight)
__device__ float g_dinv[NN];
__device__ __align__(16) float g_h0[(size_t)NN * NH];
__device__ __align__(16) float g_hA[(size_t)NN * NH];
__device__ __align__(16) float g_hB[(size_t)NN * NH];
__device__ __align__(16) float g_S [(size_t)NN * NH];   // S = 0.9*hi + 0.1*h0
__device__ __align__(16) __half g_h16A[(size_t)NN * NH];
__device__ __align__(16) __half g_h16B[(size_t)NN * NH];

// ---------------- packed fp32x2 helpers (Blackwell) ----------------
__device__ __forceinline__ ull ffma2(ull a, ull b, ull c) {
    ull d;
    asm("fma.rn.f32x2 %0, %1, %2, %3;" : "=l"(d) : "l"(a), "l"(b), "l"(c));
    return d;
}
__device__ __forceinline__ ull pack2(float s) {
    ull d;
    asm("mov.b64 %0, {%1, %1};" : "=l"(d) : "f"(s));
    return d;
}
union F2U { ull u; float2 f; };
union H2U { unsigned u; __half2 h; };

__device__ __forceinline__ unsigned h2_to_u(__half2 h) { H2U x; x.h = h; return x.u; }
__device__ __forceinline__ __half2 u_to_h2(unsigned u) { H2U x; x.u = u; return x.h; }

// ---------------- graph preprocessing ----------------
__global__ void k_zero() {
    int i = blockIdx.x * blockDim.x + threadIdx.x;
    if (i < NN) g_deg[i] = 0;
}

__global__ void k_count(const int* __restrict__ row) {
    int e = blockIdx.x * blockDim.x + threadIdx.x;
    if (e < NE) atomicAdd(&g_deg[row[e]], 1);
}

__global__ void k_dinv() {
    int i = blockIdx.x * blockDim.x + threadIdx.x;
    if (i < NN) g_dinv[i] = rsqrtf((float)(g_deg[i] + 1));  // +1 self loop
}

// coalesced 3-phase scan: block scans -> partial scan -> fixup
__global__ void __launch_bounds__(1024) k_scanA() {
    int t = threadIdx.x, b = blockIdx.x;
    int i = b * 1024 + t;
    int v = (i < NN) ? g_deg[i] : 0;
#pragma unroll
    for (int o = 1; o < 32; o <<= 1) {
        int n = __shfl_up_sync(0xffffffffu, v, o);
        if ((t & 31) >= o) v += n;
    }
    __shared__ int ws[32];
    if ((t & 31) == 31) ws[t >> 5] = v;
    __syncthreads();
    if (t < 32) {
        int s = ws[t];
#pragma unroll
        for (int o = 1; o < 32; o <<= 1) {
            int n = __shfl_up_sync(0xffffffffu, s, o);
            if (t >= o) s += n;
        }
        ws[t] = s;
    }
    __syncthreads();
    if (t >= 32) v += ws[(t >> 5) - 1];
    if (i < NN) g_incl[i] = v;
    if (t == 1023) g_bsum[b] = v;
}

__global__ void k_scanB(int nblk) {
    __shared__ int s[64];
    int t = threadIdx.x;
    s[t] = (t < nblk) ? g_bsum[t] : 0;
    __syncthreads();
    for (int o = 1; o < 64; o <<= 1) {
        int n = (t >= o) ? s[t - o] : 0;
        __syncthreads();
        s[t] += n;
        __syncthreads();
    }
    if (t < nblk) g_bsum[t] = s[t];   // inclusive
}

__global__ void __launch_bounds__(1024) k_scanC() {
    int t = threadIdx.x, b = blockIdx.x;
    int i = b * 1024 + t;
    if (i < NN) {
        int off  = b ? g_bsum[b - 1] : 0;
        int incl = g_incl[i] + off;
        int excl = incl - g_deg[i];
        g_rowptr[i] = excl;
        g_deg[i]    = excl;           // becomes fill cursor
        if (i == NN - 1) g_rowptr[NN] = incl;
    }
}

__global__ void k_scatter(const int* __restrict__ row, const int* __restrict__ col) {
    int e = blockIdx.x * blockDim.x + threadIdx.x;
    if (e < NE) {
        int r = row[e], c = col[e];
        int p = atomicAdd(&g_deg[r], 1);
        float w = g_dinv[r] * g_dinv[c];
        g_ecw[p] = (ull)(unsigned)c | ((ull)__float_as_uint(w) << 32);
    }
}

// ---------------- GEMM0: h0 = relu(x @ W0 + b0); writes h0, hA, h16A ----------------
__global__ void __launch_bounds__(256) k_gemm0(const float* __restrict__ x,
                                               const float* __restrict__ w0,
                                               const float* __restrict__ b0) {
    __shared__ __align__(16) float Wsh[64 * 128];
    __shared__ __align__(16) float Xsh[64 * 64];
    int t = threadIdx.x, lane = t & 31, warp = t >> 5;
    int row0 = blockIdx.x * 64;
    ull acc[8][2];
#pragma unroll
    for (int r = 0; r < 8; r++) { acc[r][0] = 0ULL; acc[r][1] = 0ULL; }

    for (int kc = 0; kc < NF; kc += 64) {
        const float4* wsrc = (const float4*)(w0 + (size_t)kc * NH);
        float4* wdst = (float4*)Wsh;
#pragma unroll
        for (int i = 0; i < 8; i++) wdst[t + i * 256] = wsrc[t + i * 256];
#pragma unroll
        for (int i = 0; i < 4; i++) {
            int j = t + i * 256;
            int rr = j >> 4, cc = j & 15;
            int r = row0 + rr;
            float4 v = make_float4(0.f, 0.f, 0.f, 0.f);
            if (r < NN) v = *(const float4*)(x + (size_t)r * NF + kc + (cc << 2));
            *(float4*)(Xsh + rr * 64 + (cc << 2)) = v;
        }
        __syncthreads();
        const float* sbase = Xsh + warp * 8 * 64;
#pragma unroll 2
        for (int k = 0; k < 64; k++) {
            ulonglong2 wv = *(const ulonglong2*)(Wsh + k * 128 + (lane << 2));
#pragma unroll
            for (int rr = 0; rr < 8; rr++) {
                ull sp = pack2(sbase[rr * 64 + k]);
                acc[rr][0] = ffma2(sp, wv.x, acc[rr][0]);
                acc[rr][1] = ffma2(sp, wv.y, acc[rr][1]);
            }
        }
        __syncthreads();
    }

    float4 bias = *(const float4*)(b0 + (lane << 2));
#pragma unroll
    for (int rr = 0; rr < 8; rr++) {
        int r = row0 + warp * 8 + rr;
        if (r < NN) {
            F2U u0, u1;
            u0.u = acc[rr][0];
            u1.u = acc[rr][1];
            float4 o;
            o.x = fmaxf(u0.f.x + bias.x, 0.f);
            o.y = fmaxf(u0.f.y + bias.y, 0.f);
            o.z = fmaxf(u1.f.x + bias.z, 0.f);
            o.w = fmaxf(u1.f.y + bias.w, 0.f);
            size_t off = (size_t)r * NH + (lane << 2);
            *(float4*)(g_h0 + off) = o;
            *(float4*)(g_hA + off) = o;
            uint2 p;
            p.x = h2_to_u(__floats2half2_rn(o.x, o.y));
            p.y = h2_to_u(__floats2half2_rn(o.z, o.w));
            *(uint2*)(g_h16A + off) = p;
        }
    }
}

// ---------------- SpMM + fuse: S = 0.9 * (D^-1/2 (A+I) D^-1/2 h) + 0.1 * h0 ----------------
__global__ void __launch_bounds__(256) k_spmm(int flag) {
    const __half2* __restrict__ hin16 = flag ? (const __half2*)g_h16B : (const __half2*)g_h16A;
    const float*   __restrict__ hin32 = flag ? g_hB : g_hA;
    int wid = (blockIdx.x * 256 + threadIdx.x) >> 5;
    if (wid >= NN) return;
    int lane = threadIdx.x & 31;
    int beg = g_rowptr[wid], end = g_rowptr[wid + 1];
    float di = g_dinv[wid];
    float w2 = di * di;
    float4 hv = *(const float4*)(hin32 + (size_t)wid * NH + (lane << 2));
    float4 acc = make_float4(w2 * hv.x, w2 * hv.y, w2 * hv.z, w2 * hv.w);
#pragma unroll 4
    for (int e = beg; e < end; e++) {
        ull cw = g_ecw[e];
        int   c  = (int)(unsigned)cw;
        float we = __uint_as_float((unsigned)(cw >> 32));
        uint2 raw = *(const uint2*)(hin16 + (size_t)c * 64 + (lane << 1));
        float2 f0 = __half22float2(u_to_h2(raw.x));
        float2 f1 = __half22float2(u_to_h2(raw.y));
        acc.x = fmaf(we, f0.x, acc.x);
        acc.y = fmaf(we, f0.y, acc.y);
        acc.z = fmaf(we, f1.x, acc.z);
        acc.w = fmaf(we, f1.y, acc.w);
    }
    size_t off = (size_t)wid * NH + (lane << 2);
    float4 h0v = *(const float4*)(g_h0 + off);
    float4 S;
    S.x = 0.9f * acc.x + 0.1f * h0v.x;
    S.y = 0.9f * acc.y + 0.1f * h0v.y;
    S.z = 0.9f * acc.z + 0.1f * h0v.z;
    S.w = 0.9f * acc.w + 0.1f * h0v.w;
    *(float4*)(g_S + off) = S;
}

// ---------------- layer: h = relu(theta*(S@W) + (1-theta)*S) ----------------
__global__ void __launch_bounds__(256) k_layer(const float* __restrict__ Wl, float theta, int flag) {
    float*  __restrict__ hout   = flag ? g_hA : g_hB;
    __half* __restrict__ hout16 = flag ? g_h16A : g_h16B;
    __shared__ __align__(16) float Wsh[64 * 128];
    __shared__ __align__(16) float Ssh[64 * 64];
    int t = threadIdx.x, lane = t & 31, warp = t >> 5;
    int row0 = blockIdx.x * 64;
    ull acc[8][2];
#pragma unroll
    for (int r = 0; r < 8; r++) { acc[r][0] = 0ULL; acc[r][1] = 0ULL; }

    for (int kc = 0; kc < NH; kc += 64) {
        const float4* wsrc = (const float4*)(Wl + (size_t)kc * NH);
        float4* wdst = (float4*)Wsh;
#pragma unroll
        for (int i = 0; i < 8; i++) wdst[t + i * 256] = wsrc[t + i * 256];
#pragma unroll
        for (int i = 0; i < 4; i++) {
            int j = t + i * 256;
            int rr = j >> 4, cc = j & 15;
            int r = row0 + rr;
            float4 v = make_float4(0.f, 0.f, 0.f, 0.f);
            if (r < NN) v = *(const float4*)(g_S + (size_t)r * NH + kc + (cc << 2));
            *(float4*)(Ssh + rr * 64 + (cc << 2)) = v;
        }
        __syncthreads();
        const float* sbase = Ssh + warp * 8 * 64;
#pragma unroll 2
        for (int k = 0; k < 64; k++) {
            ulonglong2 wv = *(const ulonglong2*)(Wsh + k * 128 + (lane << 2));
#pragma unroll
            for (int rr = 0; rr < 8; rr++) {
                ull sp = pack2(sbase[rr * 64 + k]);
                acc[rr][0] = ffma2(sp, wv.x, acc[rr][0]);
                acc[rr][1] = ffma2(sp, wv.y, acc[rr][1]);
            }
        }
        __syncthreads();
    }

    float omt = 1.0f - theta;
#pragma unroll
    for (int rr = 0; rr < 8; rr++) {
        int r = row0 + warp * 8 + rr;
        if (r < NN) {
            size_t off = (size_t)r * NH + (lane << 2);
            float4 s4 = *(const float4*)(g_S + off);
            F2U u0, u1;
            u0.u = acc[rr][0];
            u1.u = acc[rr][1];
            float4 o;
            o.x = fmaxf(theta * u0.f.x + omt * s4.x, 0.f);
            o.y = fmaxf(theta * u0.f.y + omt * s4.y, 0.f);
            o.z = fmaxf(theta * u1.f.x + omt * s4.z, 0.f);
            o.w = fmaxf(theta * u1.f.y + omt * s4.w, 0.f);
            *(float4*)(hout + off) = o;
            uint2 p;
            p.x = h2_to_u(__floats2half2_rn(o.x, o.y));
            p.y = h2_to_u(__floats2half2_rn(o.z, o.w));
            *(uint2*)(hout16 + off) = p;
        }
    }
}

// ---------------- final: out = hA @ fc1_w + b1 ----------------
__global__ void __launch_bounds__(256) k_final(const float* __restrict__ w1,
                                               const float* __restrict__ b1,
                                               float* __restrict__ out) {
    __shared__ __align__(16) float Wsh[64 * 128];
    __shared__ __align__(16) float Ssh[64 * 64];
    int t = threadIdx.x, lane = t & 31, warp = t >> 5;
    int row0 = blockIdx.x * 64;
    ull acc[8][2];
#pragma unroll
    for (int r = 0; r < 8; r++) { acc[r][0] = 0ULL; acc[r][1] = 0ULL; }

    for (int kc = 0; kc < NH; kc += 64) {
        const float4* wsrc = (const float4*)(w1 + (size_t)kc * NH);
        float4* wdst = (float4*)Wsh;
#pragma unroll
        for (int i = 0; i < 8; i++) wdst[t + i * 256] = wsrc[t + i * 256];
#pragma unroll
        for (int i = 0; i < 4; i++) {
            int j = t + i * 256;
            int rr = j >> 4, cc = j & 15;
            int r = row0 + rr;
            float4 v = make_float4(0.f, 0.f, 0.f, 0.f);
            if (r < NN) v = *(const float4*)(g_hA + (size_t)r * NH + kc + (cc << 2));
            *(float4*)(Ssh + rr * 64 + (cc << 2)) = v;
        }
        __syncthreads();
        const float* sbase = Ssh + warp * 8 * 64;
#pragma unroll 2
        for (int k = 0; k < 64; k++) {
            ulonglong2 wv = *(const ulonglong2*)(Wsh + k * 128 + (lane << 2));
#pragma unroll
            for (int rr = 0; rr < 8; rr++) {
                ull sp = pack2(sbase[rr * 64 + k]);
                acc[rr][0] = ffma2(sp, wv.x, acc[rr][0]);
                acc[rr][1] = ffma2(sp, wv.y, acc[rr][1]);
            }
        }
        __syncthreads();
    }

    float4 bias = *(const float4*)(b1 + (lane << 2));
#pragma unroll
    for (int rr = 0; rr < 8; rr++) {
        int r = row0 + warp * 8 + rr;
        if (r < NN) {
            F2U u0, u1;
            u0.u = acc[rr][0];
            u1.u = acc[rr][1];
            float4 o;
            o.x = u0.f.x + bias.x;
            o.y = u0.f.y + bias.y;
            o.z = u1.f.x + bias.z;
            o.w = u1.f.y + bias.w;
            *(float4*)(out + (size_t)r * NH + (lane << 2)) = o;
        }
    }
}

// ---------------- launch ----------------
extern "C" void kernel_launch(void* const* d_in, const int* in_sizes, int n_in,
                              void* d_out, int out_size) {
    const float* x    = (const float*)d_in[0];
    const int*   ei   = (const int*)d_in[1];
    const float* cw   = (const float*)d_in[2];
    const float* fc0w = (const float*)d_in[3];
    const float* fc0b = (const float*)d_in[4];
    const float* fc1w = (const float*)d_in[5];
    const float* fc1b = (const float*)d_in[6];
    float* out = (float*)d_out;

    const int* row = ei;
    const int* col = ei + NE;

    int nblk = (NN + 1023) / 1024;  // 49

    k_zero<<<(NN + 255) / 256, 256>>>();
    k_count<<<(NE + 255) / 256, 256>>>(row);
    k_dinv<<<(NN + 255) / 256, 256>>>();
    k_scanA<<<nblk, 1024>>>();
    k_scanB<<<1, 64>>>(nblk);
    k_scanC<<<nblk, 1024>>>();
    k_scatter<<<(NE + 255) / 256, 256>>>(row, col);

    int gB = (NN + 63) / 64;
    k_gemm0<<<gB, 256>>>(x, fc0w, fc0b);

    for (int l = 0; l < NL; l++) {
        int flag = l & 1;
        k_spmm<<<(NN * 32 + 255) / 256, 256>>>(flag);
        float theta = logf(0.5f / (float)(l + 1) + 1.0f);
        k_layer<<<gB, 256>>>(cw + (size_t)l * NH * NH, theta, flag);
    }

    k_final<<<gB, 256>>>(fc1w, fc1b, out);
}

// round 5
// speedup vs baseline: 1.4142x; 1.2804x over previous
#include <cuda_runtime.h>
#include <cuda_fp16.h>
#include <stdint.h>
#include <math.h>

#define NN 50000
#define NE 800000
#define NF 512
#define NH 128
#define NL 16

typedef unsigned long long ull;

// ---------------- scratch (device globals: allocation-free) ----------------
__device__ int   g_deg[NN];
__device__ int   g_rowptr[NN + 1];
__device__ int   g_incl[NN];
__device__ int   g_bsum[64];
__device__ ull   g_ecw[NE];            // packed (col, weight)
__device__ float g_dinv[NN];
__device__ __align__(16) float g_h0[(size_t)NN * NH];
__device__ __align__(16) float g_hA[(size_t)NN * NH];
__device__ __align__(16) float g_hB[(size_t)NN * NH];
__device__ __align__(16) float g_S [(size_t)NN * NH];   // S = 0.9*hi + 0.1*h0
__device__ __align__(16) __half g_h16A[(size_t)NN * NH];
__device__ __align__(16) __half g_h16B[(size_t)NN * NH];
__device__ __align__(16) __half g_w16[(size_t)NL * NH * NH];  // theta_l * W_l in fp16

// ---------------- packed fp32x2 helpers (Blackwell) ----------------
__device__ __forceinline__ ull ffma2(ull a, ull b, ull c) {
    ull d;
    asm("fma.rn.f32x2 %0, %1, %2, %3;" : "=l"(d) : "l"(a), "l"(b), "l"(c));
    return d;
}
__device__ __forceinline__ ull pack2(float s) {
    ull d;
    asm("mov.b64 %0, {%1, %1};" : "=l"(d) : "f"(s));
    return d;
}
union F2U { ull u; float2 f; };
union H2U { unsigned u; __half2 h; };

__device__ __forceinline__ unsigned h2_to_u(__half2 h) { H2U x; x.h = h; return x.u; }
__device__ __forceinline__ __half2 u_to_h2(unsigned u) { H2U x; x.u = u; return x.h; }

// ---------------- tensor-core helpers ----------------
__device__ __forceinline__ void ldsm4(unsigned &r0, unsigned &r1, unsigned &r2, unsigned &r3, unsigned addr) {
    asm volatile("ldmatrix.sync.aligned.m8n8.x4.shared.b16 {%0,%1,%2,%3}, [%4];"
                 : "=r"(r0), "=r"(r1), "=r"(r2), "=r"(r3) : "r"(addr));
}
__device__ __forceinline__ void ldsm4t(unsigned &r0, unsigned &r1, unsigned &r2, unsigned &r3, unsigned addr) {
    asm volatile("ldmatrix.sync.aligned.m8n8.x4.trans.shared.b16 {%0,%1,%2,%3}, [%4];"
                 : "=r"(r0), "=r"(r1), "=r"(r2), "=r"(r3) : "r"(addr));
}
__device__ __forceinline__ void mma16816(float* c, unsigned a0, unsigned a1, unsigned a2, unsigned a3,
                                         unsigned b0, unsigned b1) {
    asm volatile("mma.sync.aligned.m16n8k16.row.col.f32.f16.f16.f32 "
                 "{%0,%1,%2,%3}, {%4,%5,%6,%7}, {%8,%9}, {%0,%1,%2,%3};"
                 : "+f"(c[0]), "+f"(c[1]), "+f"(c[2]), "+f"(c[3])
                 : "r"(a0), "r"(a1), "r"(a2), "r"(a3), "r"(b0), "r"(b1));
}

// ---------------- graph preprocessing ----------------
__global__ void k_zero() {
    int i = blockIdx.x * blockDim.x + threadIdx.x;
    if (i < NN) g_deg[i] = 0;
}

__global__ void k_count(const int* __restrict__ row) {
    int e = blockIdx.x * blockDim.x + threadIdx.x;
    if (e < NE) atomicAdd(&g_deg[row[e]], 1);
}

__global__ void k_dinv() {
    int i = blockIdx.x * blockDim.x + threadIdx.x;
    if (i < NN) g_dinv[i] = rsqrtf((float)(g_deg[i] + 1));  // +1 self loop
}

// coalesced 3-phase scan
__global__ void __launch_bounds__(1024) k_scanA() {
    int t = threadIdx.x, b = blockIdx.x;
    int i = b * 1024 + t;
    int v = (i < NN) ? g_deg[i] : 0;
#pragma unroll
    for (int o = 1; o < 32; o <<= 1) {
        int n = __shfl_up_sync(0xffffffffu, v, o);
        if ((t & 31) >= o) v += n;
    }
    __shared__ int ws[32];
    if ((t & 31) == 31) ws[t >> 5] = v;
    __syncthreads();
    if (t < 32) {
        int s = ws[t];
#pragma unroll
        for (int o = 1; o < 32; o <<= 1) {
            int n = __shfl_up_sync(0xffffffffu, s, o);
            if (t >= o) s += n;
        }
        ws[t] = s;
    }
    __syncthreads();
    if (t >= 32) v += ws[(t >> 5) - 1];
    if (i < NN) g_incl[i] = v;
    if (t == 1023) g_bsum[b] = v;
}

__global__ void k_scanB(int nblk) {
    __shared__ int s[64];
    int t = threadIdx.x;
    s[t] = (t < nblk) ? g_bsum[t] : 0;
    __syncthreads();
    for (int o = 1; o < 64; o <<= 1) {
        int n = (t >= o) ? s[t - o] : 0;
        __syncthreads();
        s[t] += n;
        __syncthreads();
    }
    if (t < nblk) g_bsum[t] = s[t];
}

__global__ void __launch_bounds__(1024) k_scanC() {
    int t = threadIdx.x, b = blockIdx.x;
    int i = b * 1024 + t;
    if (i < NN) {
        int off  = b ? g_bsum[b - 1] : 0;
        int incl = g_incl[i] + off;
        int excl = incl - g_deg[i];
        g_rowptr[i] = excl;
        g_deg[i]    = excl;
        if (i == NN - 1) g_rowptr[NN] = incl;
    }
}

__global__ void k_scatter(const int* __restrict__ row, const int* __restrict__ col) {
    int e = blockIdx.x * blockDim.x + threadIdx.x;
    if (e < NE) {
        int r = row[e], c = col[e];
        int p = atomicAdd(&g_deg[r], 1);
        float w = g_dinv[r] * g_dinv[c];
        g_ecw[p] = (ull)(unsigned)c | ((ull)__float_as_uint(w) << 32);
    }
}

// convert conv weights to fp16 with theta folded in: g_w16[l] = theta_l * W_l
__global__ void k_wconv(const float* __restrict__ cw) {
    int idx = blockIdx.x * blockDim.x + threadIdx.x;
    if (idx < NL * NH * NH) {
        int l = idx >> 14;  // / (NH*NH)
        float theta = logf(0.5f / (float)(l + 1) + 1.0f);
        g_w16[idx] = __float2half_rn(theta * cw[idx]);
    }
}

// ---------------- GEMM0: h0 = relu(x @ W0 + b0); writes h0, hA, h16A ----------------
__global__ void __launch_bounds__(256) k_gemm0(const float* __restrict__ x,
                                               const float* __restrict__ w0,
                                               const float* __restrict__ b0) {
    __shared__ __align__(16) float Wsh[64 * 128];
    __shared__ __align__(16) float Xsh[64 * 64];
    int t = threadIdx.x, lane = t & 31, warp = t >> 5;
    int row0 = blockIdx.x * 64;
    ull acc[8][2];
#pragma unroll
    for (int r = 0; r < 8; r++) { acc[r][0] = 0ULL; acc[r][1] = 0ULL; }

    for (int kc = 0; kc < NF; kc += 64) {
        const float4* wsrc = (const float4*)(w0 + (size_t)kc * NH);
        float4* wdst = (float4*)Wsh;
#pragma unroll
        for (int i = 0; i < 8; i++) wdst[t + i * 256] = wsrc[t + i * 256];
#pragma unroll
        for (int i = 0; i < 4; i++) {
            int j = t + i * 256;
            int rr = j >> 4, cc = j & 15;
            int r = row0 + rr;
            float4 v = make_float4(0.f, 0.f, 0.f, 0.f);
            if (r < NN) v = *(const float4*)(x + (size_t)r * NF + kc + (cc << 2));
            *(float4*)(Xsh + rr * 64 + (cc << 2)) = v;
        }
        __syncthreads();
        const float* sbase = Xsh + warp * 8 * 64;
#pragma unroll 2
        for (int k = 0; k < 64; k++) {
            ulonglong2 wv = *(const ulonglong2*)(Wsh + k * 128 + (lane << 2));
#pragma unroll
            for (int rr = 0; rr < 8; rr++) {
                ull sp = pack2(sbase[rr * 64 + k]);
                acc[rr][0] = ffma2(sp, wv.x, acc[rr][0]);
                acc[rr][1] = ffma2(sp, wv.y, acc[rr][1]);
            }
        }
        __syncthreads();
    }

    float4 bias = *(const float4*)(b0 + (lane << 2));
#pragma unroll
    for (int rr = 0; rr < 8; rr++) {
        int r = row0 + warp * 8 + rr;
        if (r < NN) {
            F2U u0, u1;
            u0.u = acc[rr][0];
            u1.u = acc[rr][1];
            float4 o;
            o.x = fmaxf(u0.f.x + bias.x, 0.f);
            o.y = fmaxf(u0.f.y + bias.y, 0.f);
            o.z = fmaxf(u1.f.x + bias.z, 0.f);
            o.w = fmaxf(u1.f.y + bias.w, 0.f);
            size_t off = (size_t)r * NH + (lane << 2);
            *(float4*)(g_h0 + off) = o;
            *(float4*)(g_hA + off) = o;
            uint2 p;
            p.x = h2_to_u(__floats2half2_rn(o.x, o.y));
            p.y = h2_to_u(__floats2half2_rn(o.z, o.w));
            *(uint2*)(g_h16A + off) = p;
        }
    }
}

// ---------------- SpMM + fuse: S = 0.9 * (D^-1/2 (A+I) D^-1/2 h) + 0.1 * h0 ----------------
__global__ void __launch_bounds__(256) k_spmm(int flag) {
    const __half2* __restrict__ hin16 = flag ? (const __half2*)g_h16B : (const __half2*)g_h16A;
    const float*   __restrict__ hin32 = flag ? g_hB : g_hA;
    int wid = (blockIdx.x * 256 + threadIdx.x) >> 5;
    if (wid >= NN) return;
    int lane = threadIdx.x & 31;
    int beg = g_rowptr[wid], end = g_rowptr[wid + 1];
    float di = g_dinv[wid];
    float w2 = di * di;
    float4 hv = *(const float4*)(hin32 + (size_t)wid * NH + (lane << 2));
    float4 acc = make_float4(w2 * hv.x, w2 * hv.y, w2 * hv.z, w2 * hv.w);
#pragma unroll 4
    for (int e = beg; e < end; e++) {
        ull cw = g_ecw[e];
        int   c  = (int)(unsigned)cw;
        float we = __uint_as_float((unsigned)(cw >> 32));
        uint2 raw = *(const uint2*)(hin16 + (size_t)c * 64 + (lane << 1));
        float2 f0 = __half22float2(u_to_h2(raw.x));
        float2 f1 = __half22float2(u_to_h2(raw.y));
        acc.x = fmaf(we, f0.x, acc.x);
        acc.y = fmaf(we, f0.y, acc.y);
        acc.z = fmaf(we, f1.x, acc.z);
        acc.w = fmaf(we, f1.y, acc.w);
    }
    size_t off = (size_t)wid * NH + (lane << 2);
    float4 h0v = *(const float4*)(g_h0 + off);
    float4 S;
    S.x = 0.9f * acc.x + 0.1f * h0v.x;
    S.y = 0.9f * acc.y + 0.1f * h0v.y;
    S.z = 0.9f * acc.z + 0.1f * h0v.z;
    S.w = 0.9f * acc.w + 0.1f * h0v.w;
    *(float4*)(g_S + off) = S;
}

// ---------------- layer (tensor core): h = relu((S @ thetaW) + (1-theta)*S) ----------------
// block: 256 thr / 8 warps; tile 64 rows x 128 cols; warp: 16 rows x 64 cols
#define SPAD 72    // Ssh row stride in halves (64 + 8)
#define WPAD 136   // Wsh row stride in halves (128 + 8)
__global__ void __launch_bounds__(256) k_layer_mma(int l, float theta, int flag) {
    float*  __restrict__ hout   = flag ? g_hA : g_hB;
    __half* __restrict__ hout16 = flag ? g_h16A : g_h16B;
    const __half* __restrict__ w16 = g_w16 + (size_t)l * NH * NH;

    __shared__ __align__(16) __half Ssh[64 * SPAD];
    __shared__ __align__(16) __half Wsh[64 * WPAD];

    int t = threadIdx.x, lane = t & 31, warp = t >> 5;
    int wr = warp & 3;        // row group: rows wr*16 .. +15
    int wc = warp >> 2;       // col group: cols wc*64 .. +63
    int row0 = blockIdx.x * 64;

    float acc[8][4];
#pragma unroll
    for (int i = 0; i < 8; i++)
#pragma unroll
        for (int j = 0; j < 4; j++) acc[i][j] = 0.f;

    unsigned s_base = (unsigned)__cvta_generic_to_shared(Ssh);
    unsigned w_base = (unsigned)__cvta_generic_to_shared(Wsh);

    for (int kc = 0; kc < NH; kc += 64) {
        // load S tile [64 rows x 64 k] fp32 -> fp16 smem
#pragma unroll
        for (int i = 0; i < 4; i++) {
            int idx = t + i * 256;          // 0..1023
            int rr = idx >> 4, c4 = idx & 15;
            int r = row0 + rr;
            float4 v = make_float4(0.f, 0.f, 0.f, 0.f);
            if (r < NN) v = *(const float4*)(g_S + (size_t)r * NH + kc + (c4 << 2));
            uint2 p;
            p.x = h2_to_u(__floats2half2_rn(v.x, v.y));
            p.y = h2_to_u(__floats2half2_rn(v.z, v.w));
            *(uint2*)(Ssh + rr * SPAD + (c4 << 2)) = p;
        }
        // load W tile [64 k x 128 n] fp16
#pragma unroll
        for (int i = 0; i < 4; i++) {
            int idx = t + i * 256;          // 0..1023
            int rr = idx >> 4, c16 = idx & 15;
            uint4 v = *(const uint4*)(w16 + (size_t)(kc + rr) * NH + (c16 << 3));
            *(uint4*)(Wsh + rr * WPAD + (c16 << 3)) = v;
        }
        __syncthreads();

#pragma unroll
        for (int ks = 0; ks < 4; ks++) {
            // A fragment: rows wr*16..+15, k = ks*16..+15
            int arow = wr * 16 + (lane & 7) + ((lane >> 3) & 1) * 8;
            int acol = ks * 16 + (lane >> 4) * 8;
            unsigned a0, a1, a2, a3;
            ldsm4(a0, a1, a2, a3, s_base + (unsigned)(arow * SPAD + acol) * 2u);
#pragma unroll
            for (int nt = 0; nt < 4; nt++) {
                // B fragment: k = ks*16..+15, n = wc*64 + nt*16 ..+15
                int brow = ks * 16 + (lane & 15);
                int bcol = wc * 64 + nt * 16 + ((lane >> 4) & 1) * 8;
                unsigned b0, b1, b2, b3;
                ldsm4t(b0, b1, b2, b3, w_base + (unsigned)(brow * WPAD + bcol) * 2u);
                mma16816(acc[2 * nt],     a0, a1, a2, a3, b0, b1);
                mma16816(acc[2 * nt + 1], a0, a1, a2, a3, b2, b3);
            }
        }
        __syncthreads();
    }

    // epilogue: out = relu(acc + (1-theta)*S)
    float omt = 1.0f - theta;
    int rbase = row0 + wr * 16 + (lane >> 2);
#pragma unroll
    for (int nt = 0; nt < 8; nt++) {
        int n0 = wc * 64 + nt * 8 + (lane & 3) * 2;
#pragma unroll
        for (int half = 0; half < 2; half++) {
            int r = rbase + half * 8;
            if (r < NN) {
                size_t off = (size_t)r * NH + n0;
                float2 s = *(const float2*)(g_S + off);
                float2 o;
                o.x = fmaxf(acc[nt][2 * half]     + omt * s.x, 0.f);
                o.y = fmaxf(acc[nt][2 * half + 1] + omt * s.y, 0.f);
                *(float2*)(hout + off) = o;
                *(unsigned*)(hout16 + off) = h2_to_u(__floats2half2_rn(o.x, o.y));
            }
        }
    }
}

// ---------------- final: out = hA @ fc1_w + b1 ----------------
__global__ void __launch_bounds__(256) k_final(const float* __restrict__ w1,
                                               const float* __restrict__ b1,
                                               float* __restrict__ out) {
    __shared__ __align__(16) float Wsh[64 * 128];
    __shared__ __align__(16) float Ssh[64 * 64];
    int t = threadIdx.x, lane = t & 31, warp = t >> 5;
    int row0 = blockIdx.x * 64;
    ull acc[8][2];
#pragma unroll
    for (int r = 0; r < 8; r++) { acc[r][0] = 0ULL; acc[r][1] = 0ULL; }

    for (int kc = 0; kc < NH; kc += 64) {
        const float4* wsrc = (const float4*)(w1 + (size_t)kc * NH);
        float4* wdst = (float4*)Wsh;
#pragma unroll
        for (int i = 0; i < 8; i++) wdst[t + i * 256] = wsrc[t + i * 256];
#pragma unroll
        for (int i = 0; i < 4; i++) {
            int j = t + i * 256;
            int rr = j >> 4, cc = j & 15;
            int r = row0 + rr;
            float4 v = make_float4(0.f, 0.f, 0.f, 0.f);
            if (r < NN) v = *(const float4*)(g_hA + (size_t)r * NH + kc + (cc << 2));
            *(float4*)(Ssh + rr * 64 + (cc << 2)) = v;
        }
        __syncthreads();
        const float* sbase = Ssh + warp * 8 * 64;
#pragma unroll 2
        for (int k = 0; k < 64; k++) {
            ulonglong2 wv = *(const ulonglong2*)(Wsh + k * 128 + (lane << 2));
#pragma unroll
            for (int rr = 0; rr < 8; rr++) {
                ull sp = pack2(sbase[rr * 64 + k]);
                acc[rr][0] = ffma2(sp, wv.x, acc[rr][0]);
                acc[rr][1] = ffma2(sp, wv.y, acc[rr][1]);
            }
        }
        __syncthreads();
    }

    float4 bias = *(const float4*)(b1 + (lane << 2));
#pragma unroll
    for (int rr = 0; rr < 8; rr++) {
        int r = row0 + warp * 8 + rr;
        if (r < NN) {
            F2U u0, u1;
            u0.u = acc[rr][0];
            u1.u = acc[rr][1];
            float4 o;
            o.x = u0.f.x + bias.x;
            o.y = u0.f.y + bias.y;
            o.z = u1.f.x + bias.z;
            o.w = u1.f.y + bias.w;
            *(float4*)(out + (size_t)r * NH + (lane << 2)) = o;
        }
    }
}

// ---------------- launch ----------------
extern "C" void kernel_launch(void* const* d_in, const int* in_sizes, int n_in,
                              void* d_out, int out_size) {
    const float* x    = (const float*)d_in[0];
    const int*   ei   = (const int*)d_in[1];
    const float* cw   = (const float*)d_in[2];
    const float* fc0w = (const float*)d_in[3];
    const float* fc0b = (const float*)d_in[4];
    const float* fc1w = (const float*)d_in[5];
    const float* fc1b = (const float*)d_in[6];
    float* out = (float*)d_out;

    const int* row = ei;
    const int* col = ei + NE;

    int nblk = (NN + 1023) / 1024;  // 49

    k_zero<<<(NN + 255) / 256, 256>>>();
    k_count<<<(NE + 255) / 256, 256>>>(row);
    k_dinv<<<(NN + 255) / 256, 256>>>();
    k_scanA<<<nblk, 1024>>>();
    k_scanB<<<1, 64>>>(nblk);
    k_scanC<<<nblk, 1024>>>();
    k_scatter<<<(NE + 255) / 256, 256>>>(row, col);
    k_wconv<<<(NL * NH * NH + 255) / 256, 256>>>(cw);

    int gB = (NN + 63) / 64;
    k_gemm0<<<gB, 256>>>(x, fc0w, fc0b);

    for (int l = 0; l < NL; l++) {
        int flag = l & 1;
        k_spmm<<<(NN * 32 + 255) / 256, 256>>>(flag);
        float theta = logf(0.5f / (float)(l + 1) + 1.0f);
        k_layer_mma<<<gB, 256>>>(l, theta, flag);
    }

    k_final<<<gB, 256>>>(fc1w, fc1b, out);
}

// round 6
// speedup vs baseline: 1.5485x; 1.0950x over previous
#include <cuda_runtime.h>
#include <cuda_fp16.h>
#include <stdint.h>
#include <math.h>

#define NN 50000
#define NE 800000
#define NF 512
#define NH 128
#define NL 16

typedef unsigned long long ull;

// ---------------- scratch (device globals: allocation-free) ----------------
__device__ int   g_deg[NN];
__device__ int   g_rowptr[NN + 1];
__device__ int   g_incl[NN];
__device__ int   g_bsum[64];
__device__ ull   g_ecw[NE];            // packed (col, weight)
__device__ float g_dinv[NN];
__device__ __align__(16) float g_h0[(size_t)NN * NH];
__device__ __align__(16) float g_hA[(size_t)NN * NH];
__device__ __align__(16) float g_hB[(size_t)NN * NH];
__device__ __align__(16) float g_S [(size_t)NN * NH];   // S = 0.9*hi + 0.1*h0 (fp32)
__device__ __align__(16) __half g_S16[(size_t)NN * NH]; // S in fp16 (MMA A-tiles)
__device__ __align__(16) __half g_h16A[(size_t)NN * NH];
__device__ __align__(16) __half g_h16B[(size_t)NN * NH];
__device__ __align__(16) __half g_w16[(size_t)NL * NH * NH];  // theta_l * W_l fp16
__device__ __align__(16) __half g_w0h[(size_t)NF * NH];       // fc0_w fp16
__device__ __align__(16) __half g_w1h[(size_t)NH * NH];       // fc1_w fp16

union F2U { ull u; float2 f; };
union H2U { unsigned u; __half2 h; };
__device__ __forceinline__ unsigned h2_to_u(__half2 h) { H2U x; x.h = h; return x.u; }
__device__ __forceinline__ __half2 u_to_h2(unsigned u) { H2U x; x.u = u; return x.h; }

// ---------------- tensor-core helpers ----------------
__device__ __forceinline__ void ldsm4(unsigned &r0, unsigned &r1, unsigned &r2, unsigned &r3, unsigned addr) {
    asm volatile("ldmatrix.sync.aligned.m8n8.x4.shared.b16 {%0,%1,%2,%3}, [%4];"
                 : "=r"(r0), "=r"(r1), "=r"(r2), "=r"(r3) : "r"(addr));
}
__device__ __forceinline__ void ldsm4t(unsigned &r0, unsigned &r1, unsigned &r2, unsigned &r3, unsigned addr) {
    asm volatile("ldmatrix.sync.aligned.m8n8.x4.trans.shared.b16 {%0,%1,%2,%3}, [%4];"
                 : "=r"(r0), "=r"(r1), "=r"(r2), "=r"(r3) : "r"(addr));
}
__device__ __forceinline__ void mma16816(float* c, unsigned a0, unsigned a1, unsigned a2, unsigned a3,
                                         unsigned b0, unsigned b1) {
    asm volatile("mma.sync.aligned.m16n8k16.row.col.f32.f16.f16.f32 "
                 "{%0,%1,%2,%3}, {%4,%5,%6,%7}, {%8,%9}, {%0,%1,%2,%3};"
                 : "+f"(c[0]), "+f"(c[1]), "+f"(c[2]), "+f"(c[3])
                 : "r"(a0), "r"(a1), "r"(a2), "r"(a3), "r"(b0), "r"(b1));
}

// ---------------- graph preprocessing ----------------
__global__ void k_zero() {
    int i = blockIdx.x * blockDim.x + threadIdx.x;
    if (i < NN) g_deg[i] = 0;
}
__global__ void k_count(const int* __restrict__ row) {
    int e = blockIdx.x * blockDim.x + threadIdx.x;
    if (e < NE) atomicAdd(&g_deg[row[e]], 1);
}
__global__ void k_dinv() {
    int i = blockIdx.x * blockDim.x + threadIdx.x;
    if (i < NN) g_dinv[i] = rsqrtf((float)(g_deg[i] + 1));
}

__global__ void __launch_bounds__(1024) k_scanA() {
    int t = threadIdx.x, b = blockIdx.x;
    int i = b * 1024 + t;
    int v = (i < NN) ? g_deg[i] : 0;
#pragma unroll
    for (int o = 1; o < 32; o <<= 1) {
        int n = __shfl_up_sync(0xffffffffu, v, o);
        if ((t & 31) >= o) v += n;
    }
    __shared__ int ws[32];
    if ((t & 31) == 31) ws[t >> 5] = v;
    __syncthreads();
    if (t < 32) {
        int s = ws[t];
#pragma unroll
        for (int o = 1; o < 32; o <<= 1) {
            int n = __shfl_up_sync(0xffffffffu, s, o);
            if (t >= o) s += n;
        }
        ws[t] = s;
    }
    __syncthreads();
    if (t >= 32) v += ws[(t >> 5) - 1];
    if (i < NN) g_incl[i] = v;
    if (t == 1023) g_bsum[b] = v;
}

__global__ void k_scanB(int nblk) {
    __shared__ int s[64];
    int t = threadIdx.x;
    s[t] = (t < nblk) ? g_bsum[t] : 0;
    __syncthreads();
    for (int o = 1; o < 64; o <<= 1) {
        int n = (t >= o) ? s[t - o] : 0;
        __syncthreads();
        s[t] += n;
        __syncthreads();
    }
    if (t < nblk) g_bsum[t] = s[t];
}

__global__ void __launch_bounds__(1024) k_scanC() {
    int t = threadIdx.x, b = blockIdx.x;
    int i = b * 1024 + t;
    if (i < NN) {
        int off  = b ? g_bsum[b - 1] : 0;
        int incl = g_incl[i] + off;
        int excl = incl - g_deg[i];
        g_rowptr[i] = excl;
        g_deg[i]    = excl;
        if (i == NN - 1) g_rowptr[NN] = incl;
    }
}

__global__ void k_scatter(const int* __restrict__ row, const int* __restrict__ col) {
    int e = blockIdx.x * blockDim.x + threadIdx.x;
    if (e < NE) {
        int r = row[e], c = col[e];
        int p = atomicAdd(&g_deg[r], 1);
        float w = g_dinv[r] * g_dinv[c];
        g_ecw[p] = (ull)(unsigned)c | ((ull)__float_as_uint(w) << 32);
    }
}

// convert all weights to fp16 (conv weights with theta folded in)
__global__ void k_wcvt(const float* __restrict__ cw, const float* __restrict__ w0,
                       const float* __restrict__ w1) {
    int idx = blockIdx.x * blockDim.x + threadIdx.x;
    if (idx < NL * NH * NH) {
        int l = idx >> 14;
        float theta = logf(0.5f / (float)(l + 1) + 1.0f);
        g_w16[idx] = __float2half_rn(theta * cw[idx]);
    }
    if (idx < NF * NH) g_w0h[idx] = __float2half_rn(w0[idx]);
    if (idx < NH * NH) g_w1h[idx] = __float2half_rn(w1[idx]);
}

#define SPAD 72    // A-tile row stride in halves
#define WPAD 136   // B-tile row stride in halves

// ---------------- GEMM0 (tensor core): h0 = relu(x @ W0 + b0) ----------------
__global__ void __launch_bounds__(256) k_gemm0_mma(const float* __restrict__ x,
                                                   const float* __restrict__ b0) {
    __shared__ __align__(16) __half Ash[64 * SPAD];
    __shared__ __align__(16) __half Wsh[64 * WPAD];
    int t = threadIdx.x, lane = t & 31, warp = t >> 5;
    int wr = warp & 3, wc = warp >> 2;
    int row0 = blockIdx.x * 64;

    float acc[8][4];
#pragma unroll
    for (int i = 0; i < 8; i++)
#pragma unroll
        for (int j = 0; j < 4; j++) acc[i][j] = 0.f;

    unsigned s_base = (unsigned)__cvta_generic_to_shared(Ash);
    unsigned w_base = (unsigned)__cvta_generic_to_shared(Wsh);

    for (int kc = 0; kc < NF; kc += 64) {
        // x tile [64 x 64] fp32 -> fp16
#pragma unroll
        for (int i = 0; i < 4; i++) {
            int idx = t + i * 256;
            int rr = idx >> 4, c4 = idx & 15;
            int r = row0 + rr;
            float4 v = make_float4(0.f, 0.f, 0.f, 0.f);
            if (r < NN) v = *(const float4*)(x + (size_t)r * NF + kc + (c4 << 2));
            uint2 p;
            p.x = h2_to_u(__floats2half2_rn(v.x, v.y));
            p.y = h2_to_u(__floats2half2_rn(v.z, v.w));
            *(uint2*)(Ash + rr * SPAD + (c4 << 2)) = p;
        }
        // W0 tile [64 x 128] fp16
#pragma unroll
        for (int i = 0; i < 4; i++) {
            int idx = t + i * 256;
            int rr = idx >> 4, c16 = idx & 15;
            uint4 v = *(const uint4*)(g_w0h + (size_t)(kc + rr) * NH + (c16 << 3));
            *(uint4*)(Wsh + rr * WPAD + (c16 << 3)) = v;
        }
        __syncthreads();
#pragma unroll
        for (int ks = 0; ks < 4; ks++) {
            int arow = wr * 16 + (lane & 7) + ((lane >> 3) & 1) * 8;
            int acol = ks * 16 + (lane >> 4) * 8;
            unsigned a0, a1, a2, a3;
            ldsm4(a0, a1, a2, a3, s_base + (unsigned)(arow * SPAD + acol) * 2u);
#pragma unroll
            for (int nt = 0; nt < 4; nt++) {
                int brow = ks * 16 + (lane & 15);
                int bcol = wc * 64 + nt * 16 + ((lane >> 4) & 1) * 8;
                unsigned b0r, b1r, b2r, b3r;
                ldsm4t(b0r, b1r, b2r, b3r, w_base + (unsigned)(brow * WPAD + bcol) * 2u);
                mma16816(acc[2 * nt],     a0, a1, a2, a3, b0r, b1r);
                mma16816(acc[2 * nt + 1], a0, a1, a2, a3, b2r, b3r);
            }
        }
        __syncthreads();
    }

    int rbase = row0 + wr * 16 + (lane >> 2);
#pragma unroll
    for (int nt = 0; nt < 8; nt++) {
        int n0 = wc * 64 + nt * 8 + (lane & 3) * 2;
        float2 bias = *(const float2*)(b0 + n0);
#pragma unroll
        for (int half = 0; half < 2; half++) {
            int r = rbase + half * 8;
            if (r < NN) {
                size_t off = (size_t)r * NH + n0;
                float2 o;
                o.x = fmaxf(acc[nt][2 * half]     + bias.x, 0.f);
                o.y = fmaxf(acc[nt][2 * half + 1] + bias.y, 0.f);
                *(float2*)(g_h0 + off) = o;
                *(float2*)(g_hA + off) = o;
                *(unsigned*)(g_h16A + off) = h2_to_u(__floats2half2_rn(o.x, o.y));
            }
        }
    }
}

// ---------------- SpMM + fuse: S = 0.9*(norm-adj @ h) + 0.1*h0; writes S fp32 + fp16 ----------------
__global__ void __launch_bounds__(256) k_spmm(int flag) {
    const __half2* __restrict__ hin16 = flag ? (const __half2*)g_h16B : (const __half2*)g_h16A;
    const float*   __restrict__ hin32 = flag ? g_hB : g_hA;
    int wid = (blockIdx.x * 256 + threadIdx.x) >> 5;
    if (wid >= NN) return;
    int lane = threadIdx.x & 31;
    int beg = g_rowptr[wid], end = g_rowptr[wid + 1];
    float di = g_dinv[wid];
    float w2 = di * di;
    float4 hv = *(const float4*)(hin32 + (size_t)wid * NH + (lane << 2));
    float4 acc = make_float4(w2 * hv.x, w2 * hv.y, w2 * hv.z, w2 * hv.w);
#pragma unroll 4
    for (int e = beg; e < end; e++) {
        ull cw = g_ecw[e];
        int   c  = (int)(unsigned)cw;
        float we = __uint_as_float((unsigned)(cw >> 32));
        uint2 raw = *(const uint2*)(hin16 + (size_t)c * 64 + (lane << 1));
        float2 f0 = __half22float2(u_to_h2(raw.x));
        float2 f1 = __half22float2(u_to_h2(raw.y));
        acc.x = fmaf(we, f0.x, acc.x);
        acc.y = fmaf(we, f0.y, acc.y);
        acc.z = fmaf(we, f1.x, acc.z);
        acc.w = fmaf(we, f1.y, acc.w);
    }
    size_t off = (size_t)wid * NH + (lane << 2);
    float4 h0v = *(const float4*)(g_h0 + off);
    float4 S;
    S.x = 0.9f * acc.x + 0.1f * h0v.x;
    S.y = 0.9f * acc.y + 0.1f * h0v.y;
    S.z = 0.9f * acc.z + 0.1f * h0v.z;
    S.w = 0.9f * acc.w + 0.1f * h0v.w;
    *(float4*)(g_S + off) = S;
    uint2 p;
    p.x = h2_to_u(__floats2half2_rn(S.x, S.y));
    p.y = h2_to_u(__floats2half2_rn(S.z, S.w));
    *(uint2*)(g_S16 + off) = p;
}

// ---------------- layer (tensor core): h = relu((S @ thetaW) + (1-theta)*S) ----------------
__global__ void __launch_bounds__(256) k_layer_mma(int l, float theta, int flag) {
    float*  __restrict__ hout   = flag ? g_hA : g_hB;
    __half* __restrict__ hout16 = flag ? g_h16A : g_h16B;
    const __half* __restrict__ w16 = g_w16 + (size_t)l * NH * NH;

    __shared__ __align__(16) __half Ssh[64 * SPAD];
    __shared__ __align__(16) __half Wsh[64 * WPAD];

    int t = threadIdx.x, lane = t & 31, warp = t >> 5;
    int wr = warp & 3, wc = warp >> 2;
    int row0 = blockIdx.x * 64;

    float acc[8][4];
#pragma unroll
    for (int i = 0; i < 8; i++)
#pragma unroll
        for (int j = 0; j < 4; j++) acc[i][j] = 0.f;

    unsigned s_base = (unsigned)__cvta_generic_to_shared(Ssh);
    unsigned w_base = (unsigned)__cvta_generic_to_shared(Wsh);

    for (int kc = 0; kc < NH; kc += 64) {
        // S tile [64 x 64] fp16 direct copy
#pragma unroll
        for (int i = 0; i < 2; i++) {
            int idx = t + i * 256;          // 0..511
            int rr = idx >> 3, c8 = idx & 7;
            int r = row0 + rr;
            uint4 v = make_uint4(0u, 0u, 0u, 0u);
            if (r < NN) v = *(const uint4*)(g_S16 + (size_t)r * NH + kc + (c8 << 3));
            *(uint4*)(Ssh + rr * SPAD + (c8 << 3)) = v;
        }
        // W tile [64 x 128] fp16
#pragma unroll
        for (int i = 0; i < 4; i++) {
            int idx = t + i * 256;
            int rr = idx >> 4, c16 = idx & 15;
            uint4 v = *(const uint4*)(w16 + (size_t)(kc + rr) * NH + (c16 << 3));
            *(uint4*)(Wsh + rr * WPAD + (c16 << 3)) = v;
        }
        __syncthreads();
#pragma unroll
        for (int ks = 0; ks < 4; ks++) {
            int arow = wr * 16 + (lane & 7) + ((lane >> 3) & 1) * 8;
            int acol = ks * 16 + (lane >> 4) * 8;
            unsigned a0, a1, a2, a3;
            ldsm4(a0, a1, a2, a3, s_base + (unsigned)(arow * SPAD + acol) * 2u);
#pragma unroll
            for (int nt = 0; nt < 4; nt++) {
                int brow = ks * 16 + (lane & 15);
                int bcol = wc * 64 + nt * 16 + ((lane >> 4) & 1) * 8;
                unsigned b0, b1, b2, b3;
                ldsm4t(b0, b1, b2, b3, w_base + (unsigned)(brow * WPAD + bcol) * 2u);
                mma16816(acc[2 * nt],     a0, a1, a2, a3, b0, b1);
                mma16816(acc[2 * nt + 1], a0, a1, a2, a3, b2, b3);
            }
        }
        __syncthreads();
    }

    float omt = 1.0f - theta;
    int rbase = row0 + wr * 16 + (lane >> 2);
#pragma unroll
    for (int nt = 0; nt < 8; nt++) {
        int n0 = wc * 64 + nt * 8 + (lane & 3) * 2;
#pragma unroll
        for (int half = 0; half < 2; half++) {
            int r = rbase + half * 8;
            if (r < NN) {
                size_t off = (size_t)r * NH + n0;
                float2 s = *(const float2*)(g_S + off);
                float2 o;
                o.x = fmaxf(acc[nt][2 * half]     + omt * s.x, 0.f);
                o.y = fmaxf(acc[nt][2 * half + 1] + omt * s.y, 0.f);
                *(float2*)(hout + off) = o;
                *(unsigned*)(hout16 + off) = h2_to_u(__floats2half2_rn(o.x, o.y));
            }
        }
    }
}

// ---------------- final (tensor core): out = h16A @ fc1_w + b1 ----------------
__global__ void __launch_bounds__(256) k_final_mma(const float* __restrict__ b1,
                                                   float* __restrict__ out) {
    __shared__ __align__(16) __half Ash[64 * SPAD];
    __shared__ __align__(16) __half Wsh[64 * WPAD];
    int t = threadIdx.x, lane = t & 31, warp = t >> 5;
    int wr = warp & 3, wc = warp >> 2;
    int row0 = blockIdx.x * 64;

    float acc[8][4];
#pragma unroll
    for (int i = 0; i < 8; i++)
#pragma unroll
        for (int j = 0; j < 4; j++) acc[i][j] = 0.f;

    unsigned s_base = (unsigned)__cvta_generic_to_shared(Ash);
    unsigned w_base = (unsigned)__cvta_generic_to_shared(Wsh);

    for (int kc = 0; kc < NH; kc += 64) {
#pragma unroll
        for (int i = 0; i < 2; i++) {
            int idx = t + i * 256;
            int rr = idx >> 3, c8 = idx & 7;
            int r = row0 + rr;
            uint4 v = make_uint4(0u, 0u, 0u, 0u);
            if (r < NN) v = *(const uint4*)(g_h16A + (size_t)r * NH + kc + (c8 << 3));
            *(uint4*)(Ash + rr * SPAD + (c8 << 3)) = v;
        }
#pragma unroll
        for (int i = 0; i < 4; i++) {
            int idx = t + i * 256;
            int rr = idx >> 4, c16 = idx & 15;
            uint4 v = *(const uint4*)(g_w1h + (size_t)(kc + rr) * NH + (c16 << 3));
            *(uint4*)(Wsh + rr * WPAD + (c16 << 3)) = v;
        }
        __syncthreads();
#pragma unroll
        for (int ks = 0; ks < 4; ks++) {
            int arow = wr * 16 + (lane & 7) + ((lane >> 3) & 1) * 8;
            int acol = ks * 16 + (lane >> 4) * 8;
            unsigned a0, a1, a2, a3;
            ldsm4(a0, a1, a2, a3, s_base + (unsigned)(arow * SPAD + acol) * 2u);
#pragma unroll
            for (int nt = 0; nt < 4; nt++) {
                int brow = ks * 16 + (lane & 15);
                int bcol = wc * 64 + nt * 16 + ((lane >> 4) & 1) * 8;
                unsigned b0r, b1r, b2r, b3r;
                ldsm4t(b0r, b1r, b2r, b3r, w_base + (unsigned)(brow * WPAD + bcol) * 2u);
                mma16816(acc[2 * nt],     a0, a1, a2, a3, b0r, b1r);
                mma16816(acc[2 * nt + 1], a0, a1, a2, a3, b2r, b3r);
            }
        }
        __syncthreads();
    }

    int rbase = row0 + wr * 16 + (lane >> 2);
#pragma unroll
    for (int nt = 0; nt < 8; nt++) {
        int n0 = wc * 64 + nt * 8 + (lane & 3) * 2;
        float2 bias = *(const float2*)(b1 + n0);
#pragma unroll
        for (int half = 0; half < 2; half++) {
            int r = rbase + half * 8;
            if (r < NN) {
                size_t off = (size_t)r * NH + n0;
                float2 o;
                o.x = acc[nt][2 * half]     + bias.x;
                o.y = acc[nt][2 * half + 1] + bias.y;
                *(float2*)(out + off) = o;
            }
        }
    }
}

// ---------------- launch ----------------
extern "C" void kernel_launch(void* const* d_in, const int* in_sizes, int n_in,
                              void* d_out, int out_size) {
    const float* x    = (const float*)d_in[0];
    const int*   ei   = (const int*)d_in[1];
    const float* cw   = (const float*)d_in[2];
    const float* fc0w = (const float*)d_in[3];
    const float* fc0b = (const float*)d_in[4];
    const float* fc1w = (const float*)d_in[5];
    const float* fc1b = (const float*)d_in[6];
    float* out = (float*)d_out;

    const int* row = ei;
    const int* col = ei + NE;

    int nblk = (NN + 1023) / 1024;  // 49

    k_zero<<<(NN + 255) / 256, 256>>>();
    k_count<<<(NE + 255) / 256, 256>>>(row);
    k_dinv<<<(NN + 255) / 256, 256>>>();
    k_scanA<<<nblk, 1024>>>();
    k_scanB<<<1, 64>>>(nblk);
    k_scanC<<<nblk, 1024>>>();
    k_scatter<<<(NE + 255) / 256, 256>>>(row, col);
    k_wcvt<<<(NL * NH * NH + 255) / 256, 256>>>(cw, fc0w, fc1w);

    int gB = (NN + 63) / 64;
    k_gemm0_mma<<<gB, 256>>>(x, fc0b);

    for (int l = 0; l < NL; l++) {
        int flag = l & 1;
        k_spmm<<<(NN * 32 + 255) / 256, 256>>>(flag);
        float theta = logf(0.5f / (float)(l + 1) + 1.0f);
        k_layer_mma<<<gB, 256>>>(l, theta, flag);
    }

    k_final_mma<<<gB, 256>>>(fc1b, out);
}

// round 7
// speedup vs baseline: 1.5771x; 1.0184x over previous
#include <cuda_runtime.h>
#include <cuda_fp16.h>
#include <stdint.h>
#include <math.h>

#define NN 50000
#define NE 800000
#define NF 512
#define NH 128
#define NL 16

typedef unsigned long long ull;

// ---------------- scratch (device globals: allocation-free) ----------------
__device__ int   g_deg[NN];
__device__ int   g_rowptr[NN + 1];
__device__ int   g_incl[NN];
__device__ int   g_bsum[64];
__device__ ull   g_ecw[NE];            // packed (col, weight)
__device__ float g_dinv[NN];
__device__ __align__(16) float g_h0[(size_t)NN * NH];          // fp32 anchor
__device__ __align__(16) __half g_h16A[(size_t)NN * NH];
__device__ __align__(16) __half g_h16B[(size_t)NN * NH];
__device__ __align__(16) __half g_w16[(size_t)NL * NH * NH];   // theta_l * W_l fp16
__device__ __align__(16) __half g_w0h[(size_t)NF * NH];        // fc0_w fp16
__device__ __align__(16) __half g_w1h[(size_t)NH * NH];        // fc1_w fp16

union H2U { unsigned u; __half2 h; };
__device__ __forceinline__ unsigned h2_to_u(__half2 h) { H2U x; x.h = h; return x.u; }
__device__ __forceinline__ __half2 u_to_h2(unsigned u) { H2U x; x.u = u; return x.h; }

// ---------------- tensor-core helpers ----------------
__device__ __forceinline__ void ldsm4(unsigned &r0, unsigned &r1, unsigned &r2, unsigned &r3, unsigned addr) {
    asm volatile("ldmatrix.sync.aligned.m8n8.x4.shared.b16 {%0,%1,%2,%3}, [%4];"
                 : "=r"(r0), "=r"(r1), "=r"(r2), "=r"(r3) : "r"(addr));
}
__device__ __forceinline__ void ldsm4t(unsigned &r0, unsigned &r1, unsigned &r2, unsigned &r3, unsigned addr) {
    asm volatile("ldmatrix.sync.aligned.m8n8.x4.trans.shared.b16 {%0,%1,%2,%3}, [%4];"
                 : "=r"(r0), "=r"(r1), "=r"(r2), "=r"(r3) : "r"(addr));
}
__device__ __forceinline__ void mma16816(float* c, unsigned a0, unsigned a1, unsigned a2, unsigned a3,
                                         unsigned b0, unsigned b1) {
    asm volatile("mma.sync.aligned.m16n8k16.row.col.f32.f16.f16.f32 "
                 "{%0,%1,%2,%3}, {%4,%5,%6,%7}, {%8,%9}, {%0,%1,%2,%3};"
                 : "+f"(c[0]), "+f"(c[1]), "+f"(c[2]), "+f"(c[3])
                 : "r"(a0), "r"(a1), "r"(a2), "r"(a3), "r"(b0), "r"(b1));
}

// ---------------- graph preprocessing ----------------
__global__ void k_zero() {
    int i = blockIdx.x * blockDim.x + threadIdx.x;
    if (i < NN) g_deg[i] = 0;
}
__global__ void k_count(const int* __restrict__ row) {
    int e = blockIdx.x * blockDim.x + threadIdx.x;
    if (e < NE) atomicAdd(&g_deg[row[e]], 1);
}
__global__ void k_dinv() {
    int i = blockIdx.x * blockDim.x + threadIdx.x;
    if (i < NN) g_dinv[i] = rsqrtf((float)(g_deg[i] + 1));
}

__global__ void __launch_bounds__(1024) k_scanA() {
    int t = threadIdx.x, b = blockIdx.x;
    int i = b * 1024 + t;
    int v = (i < NN) ? g_deg[i] : 0;
#pragma unroll
    for (int o = 1; o < 32; o <<= 1) {
        int n = __shfl_up_sync(0xffffffffu, v, o);
        if ((t & 31) >= o) v += n;
    }
    __shared__ int ws[32];
    if ((t & 31) == 31) ws[t >> 5] = v;
    __syncthreads();
    if (t < 32) {
        int s = ws[t];
#pragma unroll
        for (int o = 1; o < 32; o <<= 1) {
            int n = __shfl_up_sync(0xffffffffu, s, o);
            if (t >= o) s += n;
        }
        ws[t] = s;
    }
    __syncthreads();
    if (t >= 32) v += ws[(t >> 5) - 1];
    if (i < NN) g_incl[i] = v;
    if (t == 1023) g_bsum[b] = v;
}

__global__ void k_scanB(int nblk) {
    __shared__ int s[64];
    int t = threadIdx.x;
    s[t] = (t < nblk) ? g_bsum[t] : 0;
    __syncthreads();
    for (int o = 1; o < 64; o <<= 1) {
        int n = (t >= o) ? s[t - o] : 0;
        __syncthreads();
        s[t] += n;
        __syncthreads();
    }
    if (t < nblk) g_bsum[t] = s[t];
}

__global__ void __launch_bounds__(1024) k_scanC() {
    int t = threadIdx.x, b = blockIdx.x;
    int i = b * 1024 + t;
    if (i < NN) {
        int off  = b ? g_bsum[b - 1] : 0;
        int incl = g_incl[i] + off;
        int excl = incl - g_deg[i];
        g_rowptr[i] = excl;
        g_deg[i]    = excl;
        if (i == NN - 1) g_rowptr[NN] = incl;
    }
}

__global__ void k_scatter(const int* __restrict__ row, const int* __restrict__ col) {
    int e = blockIdx.x * blockDim.x + threadIdx.x;
    if (e < NE) {
        int r = row[e], c = col[e];
        int p = atomicAdd(&g_deg[r], 1);
        float w = g_dinv[r] * g_dinv[c];
        g_ecw[p] = (ull)(unsigned)c | ((ull)__float_as_uint(w) << 32);
    }
}

__global__ void k_wcvt(const float* __restrict__ cw, const float* __restrict__ w0,
                       const float* __restrict__ w1) {
    int idx = blockIdx.x * blockDim.x + threadIdx.x;
    if (idx < NL * NH * NH) {
        int l = idx >> 14;
        float theta = logf(0.5f / (float)(l + 1) + 1.0f);
        g_w16[idx] = __float2half_rn(theta * cw[idx]);
    }
    if (idx < NF * NH) g_w0h[idx] = __float2half_rn(w0[idx]);
    if (idx < NH * NH) g_w1h[idx] = __float2half_rn(w1[idx]);
}

#define SPAD 72    // 64-wide A-tile row stride in halves (gemm0/final)
#define WPAD 136   // B-tile row stride in halves
#define KPAD 136   // fused A-tile (full K=128) row stride in halves
#define S32P 132   // fused S fp32 row stride in floats

// ---------------- GEMM0 (tensor core): h0 = relu(x @ W0 + b0) ----------------
__global__ void __launch_bounds__(256) k_gemm0_mma(const float* __restrict__ x,
                                                   const float* __restrict__ b0) {
    __shared__ __align__(16) __half Ash[64 * SPAD];
    __shared__ __align__(16) __half Wsh[64 * WPAD];
    int t = threadIdx.x, lane = t & 31, warp = t >> 5;
    int wr = warp & 3, wc = warp >> 2;
    int row0 = blockIdx.x * 64;

    float acc[8][4];
#pragma unroll
    for (int i = 0; i < 8; i++)
#pragma unroll
        for (int j = 0; j < 4; j++) acc[i][j] = 0.f;

    unsigned s_base = (unsigned)__cvta_generic_to_shared(Ash);
    unsigned w_base = (unsigned)__cvta_generic_to_shared(Wsh);

    for (int kc = 0; kc < NF; kc += 64) {
#pragma unroll
        for (int i = 0; i < 4; i++) {
            int idx = t + i * 256;
            int rr = idx >> 4, c4 = idx & 15;
            int r = row0 + rr;
            float4 v = make_float4(0.f, 0.f, 0.f, 0.f);
            if (r < NN) v = *(const float4*)(x + (size_t)r * NF + kc + (c4 << 2));
            uint2 p;
            p.x = h2_to_u(__floats2half2_rn(v.x, v.y));
            p.y = h2_to_u(__floats2half2_rn(v.z, v.w));
            *(uint2*)(Ash + rr * SPAD + (c4 << 2)) = p;
        }
#pragma unroll
        for (int i = 0; i < 4; i++) {
            int idx = t + i * 256;
            int rr = idx >> 4, c16 = idx & 15;
            uint4 v = *(const uint4*)(g_w0h + (size_t)(kc + rr) * NH + (c16 << 3));
            *(uint4*)(Wsh + rr * WPAD + (c16 << 3)) = v;
        }
        __syncthreads();
#pragma unroll
        for (int ks = 0; ks < 4; ks++) {
            int arow = wr * 16 + (lane & 7) + ((lane >> 3) & 1) * 8;
            int acol = ks * 16 + (lane >> 4) * 8;
            unsigned a0, a1, a2, a3;
            ldsm4(a0, a1, a2, a3, s_base + (unsigned)(arow * SPAD + acol) * 2u);
#pragma unroll
            for (int nt = 0; nt < 4; nt++) {
                int brow = ks * 16 + (lane & 15);
                int bcol = wc * 64 + nt * 16 + ((lane >> 4) & 1) * 8;
                unsigned b0r, b1r, b2r, b3r;
                ldsm4t(b0r, b1r, b2r, b3r, w_base + (unsigned)(brow * WPAD + bcol) * 2u);
                mma16816(acc[2 * nt],     a0, a1, a2, a3, b0r, b1r);
                mma16816(acc[2 * nt + 1], a0, a1, a2, a3, b2r, b3r);
            }
        }
        __syncthreads();
    }

    int rbase = row0 + wr * 16 + (lane >> 2);
#pragma unroll
    for (int nt = 0; nt < 8; nt++) {
        int n0 = wc * 64 + nt * 8 + (lane & 3) * 2;
        float2 bias = *(const float2*)(b0 + n0);
#pragma unroll
        for (int half = 0; half < 2; half++) {
            int r = rbase + half * 8;
            if (r < NN) {
                size_t off = (size_t)r * NH + n0;
                float2 o;
                o.x = fmaxf(acc[nt][2 * half]     + bias.x, 0.f);
                o.y = fmaxf(acc[nt][2 * half + 1] + bias.y, 0.f);
                *(float2*)(g_h0 + off) = o;
                *(unsigned*)(g_h16A + off) = h2_to_u(__floats2half2_rn(o.x, o.y));
            }
        }
    }
}

// ---------------- fused layer: SpMM (gather) + HMMA + residual epilogue ----------------
// smem layout (dynamic): Ssh32 [64][132] fp32 | Ssh16 [64][136] fp16 | Wsh [64][136] fp16
#define SMEM_S32   0
#define SMEM_S16   (64 * S32P * 4)                       // 33792
#define SMEM_W     (SMEM_S16 + 64 * KPAD * 2)            // 51200
#define SMEM_TOTAL (SMEM_W + 64 * WPAD * 2)              // 68608

__global__ void __launch_bounds__(256) k_fused(int l, float theta, int flag) {
    const __half2* __restrict__ hin16 = flag ? (const __half2*)g_h16B : (const __half2*)g_h16A;
    __half* __restrict__ hout16       = flag ? g_h16A : g_h16B;
    const __half* __restrict__ w16 = g_w16 + (size_t)l * NH * NH;

    extern __shared__ char smem[];
    float*  Ssh32 = (float*)(smem + SMEM_S32);
    __half* Ssh16 = (__half*)(smem + SMEM_S16);
    __half* Wsh   = (__half*)(smem + SMEM_W);

    int t = threadIdx.x, lane = t & 31, warp = t >> 5;
    int row0 = blockIdx.x * 64;

    // ---- phase 1: gather S = 0.9*(Â h) + 0.1*h0 into smem ----
#pragma unroll 1
    for (int j = 0; j < 8; j++) {
        int rr = warp * 8 + j;           // 0..63
        int r = row0 + rr;
        float4 S = make_float4(0.f, 0.f, 0.f, 0.f);
        if (r < NN) {
            int beg = g_rowptr[r], end = g_rowptr[r + 1];
            float di = g_dinv[r];
            float w2 = di * di;
            uint2 selfraw = *(const uint2*)(hin16 + (size_t)r * 64 + (lane << 1));
            float2 s0 = __half22float2(u_to_h2(selfraw.x));
            float2 s1 = __half22float2(u_to_h2(selfraw.y));
            float4 acc = make_float4(w2 * s0.x, w2 * s0.y, w2 * s1.x, w2 * s1.y);
#pragma unroll 4
            for (int e = beg; e < end; e++) {
                ull cw = g_ecw[e];
                int   c  = (int)(unsigned)cw;
                float we = __uint_as_float((unsigned)(cw >> 32));
                uint2 raw = *(const uint2*)(hin16 + (size_t)c * 64 + (lane << 1));
                float2 f0 = __half22float2(u_to_h2(raw.x));
                float2 f1 = __half22float2(u_to_h2(raw.y));
                acc.x = fmaf(we, f0.x, acc.x);
                acc.y = fmaf(we, f0.y, acc.y);
                acc.z = fmaf(we, f1.x, acc.z);
                acc.w = fmaf(we, f1.y, acc.w);
            }
            float4 h0v = *(const float4*)(g_h0 + (size_t)r * NH + (lane << 2));
            S.x = 0.9f * acc.x + 0.1f * h0v.x;
            S.y = 0.9f * acc.y + 0.1f * h0v.y;
            S.z = 0.9f * acc.z + 0.1f * h0v.z;
            S.w = 0.9f * acc.w + 0.1f * h0v.w;
        }
        *(float4*)(Ssh32 + rr * S32P + (lane << 2)) = S;
        uint2 p;
        p.x = h2_to_u(__floats2half2_rn(S.x, S.y));
        p.y = h2_to_u(__floats2half2_rn(S.z, S.w));
        *(uint2*)(Ssh16 + rr * KPAD + (lane << 2)) = p;
    }
    __syncthreads();

    // ---- phase 2: HMMA  acc = S16 @ (theta*W) ----
    int wr = warp & 3, wc = warp >> 2;
    float acc[8][4];
#pragma unroll
    for (int i = 0; i < 8; i++)
#pragma unroll
        for (int j = 0; j < 4; j++) acc[i][j] = 0.f;

    unsigned s_base = (unsigned)__cvta_generic_to_shared(Ssh16);
    unsigned w_base = (unsigned)__cvta_generic_to_shared(Wsh);

    for (int kc = 0; kc < NH; kc += 64) {
#pragma unroll
        for (int i = 0; i < 4; i++) {
            int idx = t + i * 256;
            int rr = idx >> 4, c16 = idx & 15;
            uint4 v = *(const uint4*)(w16 + (size_t)(kc + rr) * NH + (c16 << 3));
            *(uint4*)(Wsh + rr * WPAD + (c16 << 3)) = v;
        }
        __syncthreads();
#pragma unroll
        for (int ks = 0; ks < 4; ks++) {
            int arow = wr * 16 + (lane & 7) + ((lane >> 3) & 1) * 8;
            int acol = kc + ks * 16 + (lane >> 4) * 8;
            unsigned a0, a1, a2, a3;
            ldsm4(a0, a1, a2, a3, s_base + (unsigned)(arow * KPAD + acol) * 2u);
#pragma unroll
            for (int nt = 0; nt < 4; nt++) {
                int brow = ks * 16 + (lane & 15);
                int bcol = wc * 64 + nt * 16 + ((lane >> 4) & 1) * 8;
                unsigned b0, b1, b2, b3;
                ldsm4t(b0, b1, b2, b3, w_base + (unsigned)(brow * WPAD + bcol) * 2u);
                mma16816(acc[2 * nt],     a0, a1, a2, a3, b0, b1);
                mma16816(acc[2 * nt + 1], a0, a1, a2, a3, b2, b3);
            }
        }
        __syncthreads();
    }

    // ---- epilogue: h = relu(acc + (1-theta)*S32), write fp16 only ----
    float omt = 1.0f - theta;
    int rloc = wr * 16 + (lane >> 2);
#pragma unroll
    for (int nt = 0; nt < 8; nt++) {
        int n0 = wc * 64 + nt * 8 + (lane & 3) * 2;
#pragma unroll
        for (int half = 0; half < 2; half++) {
            int rl = rloc + half * 8;
            int r = row0 + rl;
            if (r < NN) {
                float2 s = *(const float2*)(Ssh32 + rl * S32P + n0);
                float2 o;
                o.x = fmaxf(acc[nt][2 * half]     + omt * s.x, 0.f);
                o.y = fmaxf(acc[nt][2 * half + 1] + omt * s.y, 0.f);
                *(unsigned*)(hout16 + (size_t)r * NH + n0) = h2_to_u(__floats2half2_rn(o.x, o.y));
            }
        }
    }
}

// ---------------- final (tensor core): out = h16A @ fc1_w + b1 ----------------
__global__ void __launch_bounds__(256) k_final_mma(const float* __restrict__ b1,
                                                   float* __restrict__ out) {
    __shared__ __align__(16) __half Ash[64 * SPAD];
    __shared__ __align__(16) __half Wsh[64 * WPAD];
    int t = threadIdx.x, lane = t & 31, warp = t >> 5;
    int wr = warp & 3, wc = warp >> 2;
    int row0 = blockIdx.x * 64;

    float acc[8][4];
#pragma unroll
    for (int i = 0; i < 8; i++)
#pragma unroll
        for (int j = 0; j < 4; j++) acc[i][j] = 0.f;

    unsigned s_base = (unsigned)__cvta_generic_to_shared(Ash);
    unsigned w_base = (unsigned)__cvta_generic_to_shared(Wsh);

    for (int kc = 0; kc < NH; kc += 64) {
#pragma unroll
        for (int i = 0; i < 2; i++) {
            int idx = t + i * 256;
            int rr = idx >> 3, c8 = idx & 7;
            int r = row0 + rr;
            uint4 v = make_uint4(0u, 0u, 0u, 0u);
            if (r < NN) v = *(const uint4*)(g_h16A + (size_t)r * NH + kc + (c8 << 3));
            *(uint4*)(Ash + rr * SPAD + (c8 << 3)) = v;
        }
#pragma unroll
        for (int i = 0; i < 4; i++) {
            int idx = t + i * 256;
            int rr = idx >> 4, c16 = idx & 15;
            uint4 v = *(const uint4*)(g_w1h + (size_t)(kc + rr) * NH + (c16 << 3));
            *(uint4*)(Wsh + rr * WPAD + (c16 << 3)) = v;
        }
        __syncthreads();
#pragma unroll
        for (int ks = 0; ks < 4; ks++) {
            int arow = wr * 16 + (lane & 7) + ((lane >> 3) & 1) * 8;
            int acol = ks * 16 + (lane >> 4) * 8;
            unsigned a0, a1, a2, a3;
            ldsm4(a0, a1, a2, a3, s_base + (unsigned)(arow * SPAD + acol) * 2u);
#pragma unroll
            for (int nt = 0; nt < 4; nt++) {
                int brow = ks * 16 + (lane & 15);
                int bcol = wc * 64 + nt * 16 + ((lane >> 4) & 1) * 8;
                unsigned b0r, b1r, b2r, b3r;
                ldsm4t(b0r, b1r, b2r, b3r, w_base + (unsigned)(brow * WPAD + bcol) * 2u);
                mma16816(acc[2 * nt],     a0, a1, a2, a3, b0r, b1r);
                mma16816(acc[2 * nt + 1], a0, a1, a2, a3, b2r, b3r);
            }
        }
        __syncthreads();
    }

    int rbase = row0 + wr * 16 + (lane >> 2);
#pragma unroll
    for (int nt = 0; nt < 8; nt++) {
        int n0 = wc * 64 + nt * 8 + (lane & 3) * 2;
        float2 bias = *(const float2*)(b1 + n0);
#pragma unroll
        for (int half = 0; half < 2; half++) {
            int r = rbase + half * 8;
            if (r < NN) {
                size_t off = (size_t)r * NH + n0;
                float2 o;
                o.x = acc[nt][2 * half]     + bias.x;
                o.y = acc[nt][2 * half + 1] + bias.y;
                *(float2*)(out + off) = o;
            }
        }
    }
}

// ---------------- launch ----------------
extern "C" void kernel_launch(void* const* d_in, const int* in_sizes, int n_in,
                              void* d_out, int out_size) {
    const float* x    = (const float*)d_in[0];
    const int*   ei   = (const int*)d_in[1];
    const float* cw   = (const float*)d_in[2];
    const float* fc0w = (const float*)d_in[3];
    const float* fc0b = (const float*)d_in[4];
    const float* fc1w = (const float*)d_in[5];
    const float* fc1b = (const float*)d_in[6];
    float* out = (float*)d_out;

    const int* row = ei;
    const int* col = ei + NE;

    cudaFuncSetAttribute(k_fused, cudaFuncAttributeMaxDynamicSharedMemorySize, SMEM_TOTAL);

    int nblk = (NN + 1023) / 1024;  // 49

    k_zero<<<(NN + 255) / 256, 256>>>();
    k_count<<<(NE + 255) / 256, 256>>>(row);
    k_dinv<<<(NN + 255) / 256, 256>>>();
    k_scanA<<<nblk, 1024>>>();
    k_scanB<<<1, 64>>>(nblk);
    k_scanC<<<nblk, 1024>>>();
    k_scatter<<<(NE + 255) / 256, 256>>>(row, col);
    k_wcvt<<<(NL * NH * NH + 255) / 256, 256>>>(cw, fc0w, fc1w);

    int gB = (NN + 63) / 64;
    k_gemm0_mma<<<gB, 256>>>(x, fc0b);

    for (int l = 0; l < NL; l++) {
        int flag = l & 1;
        float theta = logf(0.5f / (float)(l + 1) + 1.0f);
        k_fused<<<gB, 256, SMEM_TOTAL>>>(l, theta, flag);
    }

    k_final_mma<<<gB, 256>>>(fc1b, out);
}

// round 9
// speedup vs baseline: 1.7961x; 1.1389x over previous
#include <cuda_runtime.h>
#include <cuda_fp16.h>
#include <stdint.h>
#include <math.h>

#define NN 50000
#define NE 800000
#define NF 512
#define NH 128
#define NL 16

typedef unsigned long long ull;

// ---------------- scratch (device globals: allocation-free) ----------------
__device__ int   g_deg[NN];
__device__ int   g_rowptr[NN + 1];
__device__ int   g_incl[NN];
__device__ int   g_bsum[64];
__device__ ull   g_ecw[NE];            // packed (col, weight)
__device__ float g_dinv[NN];
__device__ __align__(16) float g_h0[(size_t)NN * NH];          // fp32 anchor
__device__ __align__(16) __half g_h16A[(size_t)NN * NH];
__device__ __align__(16) __half g_h16B[(size_t)NN * NH];
__device__ __align__(16) __half g_w16[(size_t)NL * NH * NH];   // theta_l * W_l fp16
__device__ __align__(16) __half g_w0h[(size_t)NF * NH];        // fc0_w fp16
__device__ __align__(16) __half g_w1h[(size_t)NH * NH];        // fc1_w fp16

union H2U { unsigned u; __half2 h; };
__device__ __forceinline__ unsigned h2_to_u(__half2 h) { H2U x; x.h = h; return x.u; }
__device__ __forceinline__ __half2 u_to_h2(unsigned u) { H2U x; x.u = u; return x.h; }

// ---------------- tensor-core helpers ----------------
__device__ __forceinline__ void ldsm4(unsigned &r0, unsigned &r1, unsigned &r2, unsigned &r3, unsigned addr) {
    asm volatile("ldmatrix.sync.aligned.m8n8.x4.shared.b16 {%0,%1,%2,%3}, [%4];"
                 : "=r"(r0), "=r"(r1), "=r"(r2), "=r"(r3) : "r"(addr));
}
__device__ __forceinline__ void ldsm4t(unsigned &r0, unsigned &r1, unsigned &r2, unsigned &r3, unsigned addr) {
    asm volatile("ldmatrix.sync.aligned.m8n8.x4.trans.shared.b16 {%0,%1,%2,%3}, [%4];"
                 : "=r"(r0), "=r"(r1), "=r"(r2), "=r"(r3) : "r"(addr));
}
__device__ __forceinline__ void mma16816(float* c, unsigned a0, unsigned a1, unsigned a2, unsigned a3,
                                         unsigned b0, unsigned b1) {
    asm volatile("mma.sync.aligned.m16n8k16.row.col.f32.f16.f16.f32 "
                 "{%0,%1,%2,%3}, {%4,%5,%6,%7}, {%8,%9}, {%0,%1,%2,%3};"
                 : "+f"(c[0]), "+f"(c[1]), "+f"(c[2]), "+f"(c[3])
                 : "r"(a0), "r"(a1), "r"(a2), "r"(a3), "r"(b0), "r"(b1));
}

// ---------------- graph preprocessing ----------------
__global__ void k_zero() {
    int i = blockIdx.x * blockDim.x + threadIdx.x;
    if (i < NN) g_deg[i] = 0;
}
__global__ void k_count(const int* __restrict__ row) {
    int e = blockIdx.x * blockDim.x + threadIdx.x;
    if (e < NE) atomicAdd(&g_deg[row[e]], 1);
}
__global__ void k_dinv() {
    int i = blockIdx.x * blockDim.x + threadIdx.x;
    if (i < NN) g_dinv[i] = rsqrtf((float)(g_deg[i] + 1));
}

__global__ void __launch_bounds__(1024) k_scanA() {
    int t = threadIdx.x, b = blockIdx.x;
    int i = b * 1024 + t;
    int v = (i < NN) ? g_deg[i] : 0;
#pragma unroll
    for (int o = 1; o < 32; o <<= 1) {
        int n = __shfl_up_sync(0xffffffffu, v, o);
        if ((t & 31) >= o) v += n;
    }
    __shared__ int ws[32];
    if ((t & 31) == 31) ws[t >> 5] = v;
    __syncthreads();
    if (t < 32) {
        int s = ws[t];
#pragma unroll
        for (int o = 1; o < 32; o <<= 1) {
            int n = __shfl_up_sync(0xffffffffu, s, o);
            if (t >= o) s += n;
        }
        ws[t] = s;
    }
    __syncthreads();
    if (t >= 32) v += ws[(t >> 5) - 1];
    if (i < NN) g_incl[i] = v;
    if (t == 1023) g_bsum[b] = v;
}

__global__ void k_scanB(int nblk) {
    __shared__ int s[64];
    int t = threadIdx.x;
    s[t] = (t < nblk) ? g_bsum[t] : 0;
    __syncthreads();
    for (int o = 1; o < 64; o <<= 1) {
        int n = (t >= o) ? s[t - o] : 0;
        __syncthreads();
        s[t] += n;
        __syncthreads();
    }
    if (t < nblk) g_bsum[t] = s[t];
}

__global__ void __launch_bounds__(1024) k_scanC() {
    int t = threadIdx.x, b = blockIdx.x;
    int i = b * 1024 + t;
    if (i < NN) {
        int off  = b ? g_bsum[b - 1] : 0;
        int incl = g_incl[i] + off;
        int excl = incl - g_deg[i];
        g_rowptr[i] = excl;
        g_deg[i]    = excl;
        if (i == NN - 1) g_rowptr[NN] = incl;
    }
}

__global__ void k_scatter(const int* __restrict__ row, const int* __restrict__ col) {
    int e = blockIdx.x * blockDim.x + threadIdx.x;
    if (e < NE) {
        int r = row[e], c = col[e];
        int p = atomicAdd(&g_deg[r], 1);
        float w = g_dinv[r] * g_dinv[c];
        g_ecw[p] = (ull)(unsigned)c | ((ull)__float_as_uint(w) << 32);
    }
}

__global__ void k_wcvt(const float* __restrict__ cw, const float* __restrict__ w0,
                       const float* __restrict__ w1) {
    int idx = blockIdx.x * blockDim.x + threadIdx.x;
    if (idx < NL * NH * NH) {
        int l = idx >> 14;
        float theta = logf(0.5f / (float)(l + 1) + 1.0f);
        g_w16[idx] = __float2half_rn(theta * cw[idx]);
    }
    if (idx < NF * NH) g_w0h[idx] = __float2half_rn(w0[idx]);
    if (idx < NH * NH) g_w1h[idx] = __float2half_rn(w1[idx]);
}

#define SPAD 72    // 64-wide A-tile row stride in halves (gemm0/final)
#define WPAD 136   // B-tile row stride in halves
#define KPAD 136   // fused A-tile (full K=128) row stride in halves

// ---------------- GEMM0 (tensor core): h0 = relu(x @ W0 + b0) ----------------
__global__ void __launch_bounds__(256) k_gemm0_mma(const float* __restrict__ x,
                                                   const float* __restrict__ b0) {
    __shared__ __align__(16) __half Ash[64 * SPAD];
    __shared__ __align__(16) __half Wsh[64 * WPAD];
    int t = threadIdx.x, lane = t & 31, warp = t >> 5;
    int wr = warp & 3, wc = warp >> 2;
    int row0 = blockIdx.x * 64;

    float acc[8][4];
#pragma unroll
    for (int i = 0; i < 8; i++)
#pragma unroll
        for (int j = 0; j < 4; j++) acc[i][j] = 0.f;

    unsigned s_base = (unsigned)__cvta_generic_to_shared(Ash);
    unsigned w_base = (unsigned)__cvta_generic_to_shared(Wsh);

    for (int kc = 0; kc < NF; kc += 64) {
#pragma unroll
        for (int i = 0; i < 4; i++) {
            int idx = t + i * 256;
            int rr = idx >> 4, c4 = idx & 15;
            int r = row0 + rr;
            float4 v = make_float4(0.f, 0.f, 0.f, 0.f);
            if (r < NN) v = *(const float4*)(x + (size_t)r * NF + kc + (c4 << 2));
            uint2 p;
            p.x = h2_to_u(__floats2half2_rn(v.x, v.y));
            p.y = h2_to_u(__floats2half2_rn(v.z, v.w));
            *(uint2*)(Ash + rr * SPAD + (c4 << 2)) = p;
        }
#pragma unroll
        for (int i = 0; i < 4; i++) {
            int idx = t + i * 256;
            int rr = idx >> 4, c16 = idx & 15;
            uint4 v = *(const uint4*)(g_w0h + (size_t)(kc + rr) * NH + (c16 << 3));
            *(uint4*)(Wsh + rr * WPAD + (c16 << 3)) = v;
        }
        __syncthreads();
#pragma unroll
        for (int ks = 0; ks < 4; ks++) {
            int arow = wr * 16 + (lane & 7) + ((lane >> 3) & 1) * 8;
            int acol = ks * 16 + (lane >> 4) * 8;
            unsigned a0, a1, a2, a3;
            ldsm4(a0, a1, a2, a3, s_base + (unsigned)(arow * SPAD + acol) * 2u);
#pragma unroll
            for (int nt = 0; nt < 4; nt++) {
                int brow = ks * 16 + (lane & 15);
                int bcol = wc * 64 + nt * 16 + ((lane >> 4) & 1) * 8;
                unsigned b0r, b1r, b2r, b3r;
                ldsm4t(b0r, b1r, b2r, b3r, w_base + (unsigned)(brow * WPAD + bcol) * 2u);
                mma16816(acc[2 * nt],     a0, a1, a2, a3, b0r, b1r);
                mma16816(acc[2 * nt + 1], a0, a1, a2, a3, b2r, b3r);
            }
        }
        __syncthreads();
    }

    int rbase = row0 + wr * 16 + (lane >> 2);
#pragma unroll
    for (int nt = 0; nt < 8; nt++) {
        int n0 = wc * 64 + nt * 8 + (lane & 3) * 2;
        float2 bias = *(const float2*)(b0 + n0);
#pragma unroll
        for (int half = 0; half < 2; half++) {
            int r = rbase + half * 8;
            if (r < NN) {
                size_t off = (size_t)r * NH + n0;
                float2 o;
                o.x = fmaxf(acc[nt][2 * half]     + bias.x, 0.f);
                o.y = fmaxf(acc[nt][2 * half + 1] + bias.y, 0.f);
                *(float2*)(g_h0 + off) = o;
                *(unsigned*)(g_h16A + off) = h2_to_u(__floats2half2_rn(o.x, o.y));
            }
        }
    }
}

// ---------------- fused layer: SpMM gather + HMMA + residual epilogue ----------------
// smem: Ssh16 [64][136] fp16 | Wsh [64][136] fp16   (34.8 KB static)
__global__ void __launch_bounds__(256, 4) k_fused(int l, float theta, int flag) {
    const __half2* __restrict__ hin16 = flag ? (const __half2*)g_h16B : (const __half2*)g_h16A;
    __half* __restrict__ hout16       = flag ? g_h16A : g_h16B;
    const __half* __restrict__ w16 = g_w16 + (size_t)l * NH * NH;

    __shared__ __align__(16) __half Ssh16[64 * KPAD];
    __shared__ __align__(16) __half Wsh[64 * WPAD];

    int t = threadIdx.x, lane = t & 31, warp = t >> 5;
    int row0 = blockIdx.x * 64;

    // ---- phase 1: gather S = 0.9*(Â h) + 0.1*h0, dual-row per warp for MLP ----
#pragma unroll 1
    for (int jp = 0; jp < 4; jp++) {
        int rrA = warp * 8 + jp * 2;
        int rrB = rrA + 1;
        int rA = row0 + rrA, rB = row0 + rrB;

        float4 aA = make_float4(0.f, 0.f, 0.f, 0.f);
        float4 aB = make_float4(0.f, 0.f, 0.f, 0.f);
        int e0 = 0, end0 = 0, e1 = 0, end1 = 0;

        if (rA < NN) {
            e0 = g_rowptr[rA]; end0 = g_rowptr[rA + 1];
            float di = g_dinv[rA]; float w2 = di * di;
            uint2 sr = *(const uint2*)(hin16 + (size_t)rA * 64 + (lane << 1));
            float2 s0 = __half22float2(u_to_h2(sr.x));
            float2 s1 = __half22float2(u_to_h2(sr.y));
            aA = make_float4(w2 * s0.x, w2 * s0.y, w2 * s1.x, w2 * s1.y);
        }
        if (rB < NN) {
            e1 = g_rowptr[rB]; end1 = g_rowptr[rB + 1];
            float di = g_dinv[rB]; float w2 = di * di;
            uint2 sr = *(const uint2*)(hin16 + (size_t)rB * 64 + (lane << 1));
            float2 s0 = __half22float2(u_to_h2(sr.x));
            float2 s1 = __half22float2(u_to_h2(sr.y));
            aB = make_float4(w2 * s0.x, w2 * s0.y, w2 * s1.x, w2 * s1.y);
        }

        // interleaved dual-row edge loop (2 independent load chains)
#pragma unroll 2
        while (e0 < end0 && e1 < end1) {
            ull cwA = g_ecw[e0];
            ull cwB = g_ecw[e1];
            int   cA = (int)(unsigned)cwA;
            int   cB = (int)(unsigned)cwB;
            float wA = __uint_as_float((unsigned)(cwA >> 32));
            float wB = __uint_as_float((unsigned)(cwB >> 32));
            uint2 rawA = *(const uint2*)(hin16 + (size_t)cA * 64 + (lane << 1));
            uint2 rawB = *(const uint2*)(hin16 + (size_t)cB * 64 + (lane << 1));
            float2 fA0 = __half22float2(u_to_h2(rawA.x));
            float2 fA1 = __half22float2(u_to_h2(rawA.y));
            float2 fB0 = __half22float2(u_to_h2(rawB.x));
            float2 fB1 = __half22float2(u_to_h2(rawB.y));
            aA.x = fmaf(wA, fA0.x, aA.x); aA.y = fmaf(wA, fA0.y, aA.y);
            aA.z = fmaf(wA, fA1.x, aA.z); aA.w = fmaf(wA, fA1.y, aA.w);
            aB.x = fmaf(wB, fB0.x, aB.x); aB.y = fmaf(wB, fB0.y, aB.y);
            aB.z = fmaf(wB, fB1.x, aB.z); aB.w = fmaf(wB, fB1.y, aB.w);
            e0++; e1++;
        }
#pragma unroll 4
        while (e0 < end0) {
            ull cw = g_ecw[e0++];
            int   c  = (int)(unsigned)cw;
            float we = __uint_as_float((unsigned)(cw >> 32));
            uint2 raw = *(const uint2*)(hin16 + (size_t)c * 64 + (lane << 1));
            float2 f0 = __half22float2(u_to_h2(raw.x));
            float2 f1 = __half22float2(u_to_h2(raw.y));
            aA.x = fmaf(we, f0.x, aA.x); aA.y = fmaf(we, f0.y, aA.y);
            aA.z = fmaf(we, f1.x, aA.z); aA.w = fmaf(we, f1.y, aA.w);
        }
#pragma unroll 4
        while (e1 < end1) {
            ull cw = g_ecw[e1++];
            int   c  = (int)(unsigned)cw;
            float we = __uint_as_float((unsigned)(cw >> 32));
            uint2 raw = *(const uint2*)(hin16 + (size_t)c * 64 + (lane << 1));
            float2 f0 = __half22float2(u_to_h2(raw.x));
            float2 f1 = __half22float2(u_to_h2(raw.y));
            aB.x = fmaf(we, f0.x, aB.x); aB.y = fmaf(we, f0.y, aB.y);
            aB.z = fmaf(we, f1.x, aB.z); aB.w = fmaf(we, f1.y, aB.w);
        }

        // S = 0.9*acc + 0.1*h0 -> fp16 smem
        if (rA < NN) {
            float4 h0v = *(const float4*)(g_h0 + (size_t)rA * NH + (lane << 2));
            float4 S;
            S.x = 0.9f * aA.x + 0.1f * h0v.x;
            S.y = 0.9f * aA.y + 0.1f * h0v.y;
            S.z = 0.9f * aA.z + 0.1f * h0v.z;
            S.w = 0.9f * aA.w + 0.1f * h0v.w;
            uint2 p;
            p.x = h2_to_u(__floats2half2_rn(S.x, S.y));
            p.y = h2_to_u(__floats2half2_rn(S.z, S.w));
            *(uint2*)(Ssh16 + rrA * KPAD + (lane << 2)) = p;
        } else {
            *(uint2*)(Ssh16 + rrA * KPAD + (lane << 2)) = make_uint2(0u, 0u);
        }
        if (rB < NN) {
            float4 h0v = *(const float4*)(g_h0 + (size_t)rB * NH + (lane << 2));
            float4 S;
            S.x = 0.9f * aB.x + 0.1f * h0v.x;
            S.y = 0.9f * aB.y + 0.1f * h0v.y;
            S.z = 0.9f * aB.z + 0.1f * h0v.z;
            S.w = 0.9f * aB.w + 0.1f * h0v.w;
            uint2 p;
            p.x = h2_to_u(__floats2half2_rn(S.x, S.y));
            p.y = h2_to_u(__floats2half2_rn(S.z, S.w));
            *(uint2*)(Ssh16 + rrB * KPAD + (lane << 2)) = p;
        } else {
            *(uint2*)(Ssh16 + rrB * KPAD + (lane << 2)) = make_uint2(0u, 0u);
        }
    }
    __syncthreads();

    // ---- phase 2: HMMA  acc = S16 @ (theta*W) ----
    int wr = warp & 3, wc = warp >> 2;
    float acc[8][4];
#pragma unroll
    for (int i = 0; i < 8; i++)
#pragma unroll
        for (int j = 0; j < 4; j++) acc[i][j] = 0.f;

    unsigned s_base = (unsigned)__cvta_generic_to_shared(Ssh16);
    unsigned w_base = (unsigned)__cvta_generic_to_shared(Wsh);

    for (int kc = 0; kc < NH; kc += 64) {
#pragma unroll
        for (int i = 0; i < 4; i++) {
            int idx = t + i * 256;
            int rr = idx >> 4, c16 = idx & 15;
            uint4 v = *(const uint4*)(w16 + (size_t)(kc + rr) * NH + (c16 << 3));
            *(uint4*)(Wsh + rr * WPAD + (c16 << 3)) = v;
        }
        __syncthreads();
#pragma unroll
        for (int ks = 0; ks < 4; ks++) {
            int arow = wr * 16 + (lane & 7) + ((lane >> 3) & 1) * 8;
            int acol = kc + ks * 16 + (lane >> 4) * 8;
            unsigned a0, a1, a2, a3;
            ldsm4(a0, a1, a2, a3, s_base + (unsigned)(arow * KPAD + acol) * 2u);
#pragma unroll
            for (int nt = 0; nt < 4; nt++) {
                int brow = ks * 16 + (lane & 15);
                int bcol = wc * 64 + nt * 16 + ((lane >> 4) & 1) * 8;
                unsigned b0, b1, b2, b3;
                ldsm4t(b0, b1, b2, b3, w_base + (unsigned)(brow * WPAD + bcol) * 2u);
                mma16816(acc[2 * nt],     a0, a1, a2, a3, b0, b1);
                mma16816(acc[2 * nt + 1], a0, a1, a2, a3, b2, b3);
            }
        }
        __syncthreads();
    }

    // ---- epilogue: h = relu(acc + (1-theta)*S16), write fp16 ----
    float omt = 1.0f - theta;
    int rloc = wr * 16 + (lane >> 2);
#pragma unroll
    for (int nt = 0; nt < 8; nt++) {
        int n0 = wc * 64 + nt * 8 + (lane & 3) * 2;
#pragma unroll
        for (int half = 0; half < 2; half++) {
            int rl = rloc + half * 8;
            int r = row0 + rl;
            if (r < NN) {
                float2 s = __half22float2(u_to_h2(*(const unsigned*)(Ssh16 + rl * KPAD + n0)));
                float2 o;
                o.x = fmaxf(acc[nt][2 * half]     + omt * s.x, 0.f);
                o.y = fmaxf(acc[nt][2 * half + 1] + omt * s.y, 0.f);
                *(unsigned*)(hout16 + (size_t)r * NH + n0) = h2_to_u(__floats2half2_rn(o.x, o.y));
            }
        }
    }
}

// ---------------- final (tensor core): out = h16A @ fc1_w + b1 ----------------
__global__ void __launch_bounds__(256) k_final_mma(const float* __restrict__ b1,
                                                   float* __restrict__ out) {
    __shared__ __align__(16) __half Ash[64 * SPAD];
    __shared__ __align__(16) __half Wsh[64 * WPAD];
    int t = threadIdx.x, lane = t & 31, warp = t >> 5;
    int wr = warp & 3, wc = warp >> 2;
    int row0 = blockIdx.x * 64;

    float acc[8][4];
#pragma unroll
    for (int i = 0; i < 8; i++)
#pragma unroll
        for (int j = 0; j < 4; j++) acc[i][j] = 0.f;

    unsigned s_base = (unsigned)__cvta_generic_to_shared(Ash);
    unsigned w_base = (unsigned)__cvta_generic_to_shared(Wsh);

    for (int kc = 0; kc < NH; kc += 64) {
#pragma unroll
        for (int i = 0; i < 2; i++) {
            int idx = t + i * 256;
            int rr = idx >> 3, c8 = idx & 7;
            int r = row0 + rr;
            uint4 v = make_uint4(0u, 0u, 0u, 0u);
            if (r < NN) v = *(const uint4*)(g_h16A + (size_t)r * NH + kc + (c8 << 3));
            *(uint4*)(Ash + rr * SPAD + (c8 << 3)) = v;
        }
#pragma unroll
        for (int i = 0; i < 4; i++) {
            int idx = t + i * 256;
            int rr = idx >> 4, c16 = idx & 15;
            uint4 v = *(const uint4*)(g_w1h + (size_t)(kc + rr) * NH + (c16 << 3));
            *(uint4*)(Wsh + rr * WPAD + (c16 << 3)) = v;
        }
        __syncthreads();
#pragma unroll
        for (int ks = 0; ks < 4; ks++) {
            int arow = wr * 16 + (lane & 7) + ((lane >> 3) & 1) * 8;
            int acol = ks * 16 + (lane >> 4) * 8;
            unsigned a0, a1, a2, a3;
            ldsm4(a0, a1, a2, a3, s_base + (unsigned)(arow * SPAD + acol) * 2u);
#pragma unroll
            for (int nt = 0; nt < 4; nt++) {
                int brow = ks * 16 + (lane & 15);
                int bcol = wc * 64 + nt * 16 + ((lane >> 4) & 1) * 8;
                unsigned b0r, b1r, b2r, b3r;
                ldsm4t(b0r, b1r, b2r, b3r, w_base + (unsigned)(brow * WPAD + bcol) * 2u);
                mma16816(acc[2 * nt],     a0, a1, a2, a3, b0r, b1r);
                mma16816(acc[2 * nt + 1], a0, a1, a2, a3, b2r, b3r);
            }
        }
        __syncthreads();
    }

    int rbase = row0 + wr * 16 + (lane >> 2);
#pragma unroll
    for (int nt = 0; nt < 8; nt++) {
        int n0 = wc * 64 + nt * 8 + (lane & 3) * 2;
        float2 bias = *(const float2*)(b1 + n0);
#pragma unroll
        for (int half = 0; half < 2; half++) {
            int r = rbase + half * 8;
            if (r < NN) {
                size_t off = (size_t)r * NH + n0;
                float2 o;
                o.x = acc[nt][2 * half]     + bias.x;
                o.y = acc[nt][2 * half + 1] + bias.y;
                *(float2*)(out + off) = o;
            }
        }
    }
}

// ---------------- launch ----------------
extern "C" void kernel_launch(void* const* d_in, const int* in_sizes, int n_in,
                              void* d_out, int out_size) {
    const float* x    = (const float*)d_in[0];
    const int*   ei   = (const int*)d_in[1];
    const float* cw   = (const float*)d_in[2];
    const float* fc0w = (const float*)d_in[3];
    const float* fc0b = (const float*)d_in[4];
    const float* fc1w = (const float*)d_in[5];
    const float* fc1b = (const float*)d_in[6];
    float* out = (float*)d_out;

    const int* row = ei;
    const int* col = ei + NE;

    int nblk = (NN + 1023) / 1024;  // 49

    k_zero<<<(NN + 255) / 256, 256>>>();
    k_count<<<(NE + 255) / 256, 256>>>(row);
    k_dinv<<<(NN + 255) / 256, 256>>>();
    k_scanA<<<nblk, 1024>>>();
    k_scanB<<<1, 64>>>(nblk);
    k_scanC<<<nblk, 1024>>>();
    k_scatter<<<(NE + 255) / 256, 256>>>(row, col);
    k_wcvt<<<(NL * NH * NH + 255) / 256, 256>>>(cw, fc0w, fc1w);

    int gB = (NN + 63) / 64;
    k_gemm0_mma<<<gB, 256>>>(x, fc0b);

    for (int l = 0; l < NL; l++) {
        int flag = l & 1;
        float theta = logf(0.5f / (float)(l + 1) + 1.0f);
        k_fused<<<gB, 256>>>(l, theta, flag);
    }

    k_final_mma<<<gB, 256>>>(fc1b, out);
}